// round 1
// baseline (speedup 1.0000x reference)
#include <cuda_runtime.h>
#include <cuda_bf16.h>

// Problem constants (fixed by the dataset)
#define NN   50000      // nodes
#define EE   800000     // edges (excluding self loops)
#define FIN  128        // input features
#define H1   8          // heads layer 1
#define C1   32         // channels/head layer 1
#define HC   256        // H1*C1
#define CO   10         // out channels layer 2
#define NG   128        // graphs
#define NEG_SLOPE 0.2f

// ---------------- scratch (device globals; no runtime allocation) ----------
__device__ float g_xh[NN * HC];        // layer1 transformed features
__device__ float g_h1[NN * HC];        // layer1 output (post elu)
__device__ float g_as1[NN * H1];
__device__ float g_ad1[NN * H1];
__device__ int   g_deg[NN];
__device__ int   g_off[NN + 1];
__device__ int   g_cur[NN];
__device__ int   g_ssrc[EE];           // edge srcs sorted by dst (CSR)
__device__ float g_xh2[NN * CO];
__device__ float g_as2[NN];
__device__ float g_ad2[NN];
__device__ float g_sums[NG * CO];
__device__ float g_cnt[NG];

__device__ __forceinline__ float lrelu(float x) {
    return fmaxf(x, 0.0f) + NEG_SLOPE * fminf(x, 0.0f);
}
__device__ __forceinline__ float elu(float x) {
    return x > 0.0f ? x : (__expf(x) - 1.0f);
}

// ---------------- 0. zero counters ----------------------------------------
__global__ void k_zero() {
    int i = blockIdx.x * blockDim.x + threadIdx.x;
    if (i < NN) g_deg[i] = 0;
    if (i < NG * CO) g_sums[i] = 0.0f;
    if (i < NG) g_cnt[i] = 0.0f;
}

// ---------------- 1. GEMM1: xh = x @ W1  (50000x128 @ 128x256) -------------
#define BM 64
#define BN 64
#define BK 32
__global__ void k_gemm1(const float* __restrict__ x, const float* __restrict__ W) {
    __shared__ float AsT[BK][BM];   // transposed A tile
    __shared__ float Bs[BK][BN];
    const int tid = threadIdx.x;
    const int bm = blockIdx.x * BM;
    const int bn = blockIdx.y * BN;
    const int tx = tid & 15;        // 16 cols of threads
    const int ty = tid >> 4;        // 16 rows of threads
    float acc[4][4];
#pragma unroll
    for (int r = 0; r < 4; r++)
#pragma unroll
        for (int c = 0; c < 4; c++) acc[r][c] = 0.0f;

    for (int k0 = 0; k0 < FIN; k0 += BK) {
        // load A tile: each thread 8 floats (two float4), rows of x
        {
            int ar = tid >> 2;              // 0..63
            int ac = (tid & 3) * 8;         // 0,8,16,24
            float4 a0, a1;
            if (bm + ar < NN) {
                const float4* p = (const float4*)(x + (size_t)(bm + ar) * FIN + k0 + ac);
                a0 = p[0]; a1 = p[1];
            } else {
                a0 = make_float4(0.f, 0.f, 0.f, 0.f); a1 = a0;
            }
            AsT[ac + 0][ar] = a0.x; AsT[ac + 1][ar] = a0.y;
            AsT[ac + 2][ar] = a0.z; AsT[ac + 3][ar] = a0.w;
            AsT[ac + 4][ar] = a1.x; AsT[ac + 5][ar] = a1.y;
            AsT[ac + 6][ar] = a1.z; AsT[ac + 7][ar] = a1.w;
        }
        // load B tile: 32 rows x 64 cols
        {
            int br = tid >> 3;              // 0..31
            int bc = (tid & 7) * 8;         // 0..56
            const float4* q = (const float4*)(W + (size_t)(k0 + br) * HC + bn + bc);
            float4 b0 = q[0], b1 = q[1];
            *(float4*)&Bs[br][bc] = b0;
            *(float4*)&Bs[br][bc + 4] = b1;
        }
        __syncthreads();
#pragma unroll
        for (int kk = 0; kk < BK; kk++) {
            float a[4], b[4];
            float4 av = *(const float4*)&AsT[kk][ty * 4];
            a[0] = av.x; a[1] = av.y; a[2] = av.z; a[3] = av.w;
            float4 bv = *(const float4*)&Bs[kk][tx * 4];
            b[0] = bv.x; b[1] = bv.y; b[2] = bv.z; b[3] = bv.w;
#pragma unroll
            for (int r = 0; r < 4; r++)
#pragma unroll
                for (int c = 0; c < 4; c++) acc[r][c] = fmaf(a[r], b[c], acc[r][c]);
        }
        __syncthreads();
    }
#pragma unroll
    for (int r = 0; r < 4; r++) {
        int row = bm + ty * 4 + r;
        if (row < NN) {
            float4 v = make_float4(acc[r][0], acc[r][1], acc[r][2], acc[r][3]);
            *(float4*)&g_xh[(size_t)row * HC + bn + tx * 4] = v;
        }
    }
}

// ---------------- 2. per-node attention scalars layer1 ---------------------
__global__ void k_attn1(const float* __restrict__ att_src, const float* __restrict__ att_dst) {
    int warp = threadIdx.x >> 5;
    int lane = threadIdx.x & 31;
    int n = blockIdx.x * 8 + warp;
    if (n >= NN) return;
    const float* row = g_xh + (size_t)n * HC;
#pragma unroll
    for (int h = 0; h < H1; h++) {
        float v = row[h * C1 + lane];
        float ps = v * att_src[h * C1 + lane];
        float pd = v * att_dst[h * C1 + lane];
#pragma unroll
        for (int o = 16; o; o >>= 1) {
            ps += __shfl_xor_sync(0xffffffffu, ps, o);
            pd += __shfl_xor_sync(0xffffffffu, pd, o);
        }
        if (lane == 0) {
            g_as1[n * H1 + h] = ps;
            g_ad1[n * H1 + h] = pd;
        }
    }
}

// ---------------- 3. degree histogram --------------------------------------
__global__ void k_hist(const int* __restrict__ ei, int E) {
    int e = blockIdx.x * blockDim.x + threadIdx.x;
    if (e < E) atomicAdd(&g_deg[ei[E + e]], 1);
}

// ---------------- 4. exclusive scan (single block) --------------------------
__global__ void k_scan() {
    const int T = 1024;
    const int per = (NN + T - 1) / T;   // 49
    int t = threadIdx.x;
    int b = t * per;
    int local = 0;
    for (int i = 0; i < per; i++) {
        int idx = b + i;
        if (idx < NN) local += g_deg[idx];
    }
    __shared__ int s[T];
    s[t] = local;
    __syncthreads();
    for (int o = 1; o < T; o <<= 1) {
        int v = (t >= o) ? s[t - o] : 0;
        __syncthreads();
        s[t] += v;
        __syncthreads();
    }
    int base = (t > 0) ? s[t - 1] : 0;
    int run = base;
    for (int i = 0; i < per; i++) {
        int idx = b + i;
        if (idx < NN) {
            g_off[idx] = run;
            g_cur[idx] = run;
            run += g_deg[idx];
        }
    }
    if (t == T - 1) g_off[NN] = s[T - 1];
}

// ---------------- 5. scatter edges into CSR ---------------------------------
__global__ void k_scatter(const int* __restrict__ ei, int E) {
    int e = blockIdx.x * blockDim.x + threadIdx.x;
    if (e < E) {
        int d = ei[E + e];
        int p = atomicAdd(&g_cur[d], 1);
        g_ssrc[p] = ei[e];
    }
}

// ---------------- 6. layer-1 aggregation: softmax-weighted gather -----------
// one block per node, 8 warps = 8 heads, 32 lanes = 32 channels
__global__ void k_agg1(const float* __restrict__ b1) {
    int n = blockIdx.x;
    int h = threadIdx.x >> 5;
    int lane = threadIdx.x & 31;
    float ad = g_ad1[n * H1 + h];
    int beg = g_off[n], end = g_off[n + 1];
    // pass 1: max (include self loop)
    float m = lrelu(g_as1[n * H1 + h] + ad);
    for (int e = beg; e < end; e++) {
        int s = g_ssrc[e];
        float al = lrelu(g_as1[s * H1 + h] + ad);
        m = fmaxf(m, al);
    }
    // pass 2: weighted accumulate (self loop first)
    float w = __expf(lrelu(g_as1[n * H1 + h] + ad) - m);
    float wsum = w;
    float acc = w * g_xh[(size_t)n * HC + h * C1 + lane];
    for (int e = beg; e < end; e++) {
        int s = g_ssrc[e];
        float al = lrelu(g_as1[s * H1 + h] + ad);
        float we = __expf(al - m);
        wsum += we;
        acc = fmaf(we, g_xh[(size_t)s * HC + h * C1 + lane], acc);
    }
    float out = acc / wsum + b1[h * C1 + lane];
    g_h1[(size_t)n * HC + h * C1 + lane] = elu(out);
}

// ---------------- 7. layer-2 GEMV + attention scalars ------------------------
__global__ void k_gemm2(const float* __restrict__ W2,
                        const float* __restrict__ att_src2,
                        const float* __restrict__ att_dst2) {
    int warp = threadIdx.x >> 5;
    int lane = threadIdx.x & 31;
    int n = blockIdx.x * 8 + warp;
    if (n >= NN) return;
    float hreg[8];
    const float* row = g_h1 + (size_t)n * HC;
#pragma unroll
    for (int j = 0; j < 8; j++) hreg[j] = row[j * 32 + lane];
    float a_s = 0.f, a_d = 0.f;
#pragma unroll
    for (int c = 0; c < CO; c++) {
        float p = 0.f;
#pragma unroll
        for (int j = 0; j < 8; j++) p = fmaf(hreg[j], W2[(j * 32 + lane) * CO + c], p);
#pragma unroll
        for (int o = 16; o; o >>= 1) p += __shfl_xor_sync(0xffffffffu, p, o);
        if (lane == 0) {
            g_xh2[n * CO + c] = p;
            a_s = fmaf(p, att_src2[c], a_s);
            a_d = fmaf(p, att_dst2[c], a_d);
        }
    }
    if (lane == 0) {
        g_as2[n] = a_s;
        g_ad2[n] = a_d;
    }
}

// ---------------- 8. layer-2 aggregation + fused mean-pool atomics -----------
__global__ void k_agg2(const int* __restrict__ batch, const float* __restrict__ b2) {
    int warp = threadIdx.x >> 5;
    int lane = threadIdx.x & 31;
    int n = blockIdx.x * 8 + warp;
    if (n >= NN) return;
    float ad = g_ad2[n];
    int beg = g_off[n], end = g_off[n + 1];
    float m = lrelu(g_as2[n] + ad);
    for (int e = beg; e < end; e++) {
        float al = lrelu(g_as2[g_ssrc[e]] + ad);
        m = fmaxf(m, al);
    }
    float w = __expf(lrelu(g_as2[n] + ad) - m);
    float wsum = w;
    float acc = (lane < CO) ? w * g_xh2[n * CO + lane] : 0.f;
    for (int e = beg; e < end; e++) {
        int s = g_ssrc[e];
        float al = lrelu(g_as2[s] + ad);
        float we = __expf(al - m);
        wsum += we;
        if (lane < CO) acc = fmaf(we, g_xh2[s * CO + lane], acc);
    }
    if (lane < CO) {
        float out = elu(acc / wsum + b2[lane]);
        atomicAdd(&g_sums[batch[n] * CO + lane], out);
    }
    if (lane == 0) atomicAdd(&g_cnt[batch[n]], 1.0f);
}

// ---------------- 9. mean + log_softmax -------------------------------------
__global__ void k_final(float* __restrict__ out) {
    int g = threadIdx.x;
    if (g >= NG) return;
    float inv = 1.0f / fmaxf(g_cnt[g], 1.0f);
    float v[CO];
    float mx = -1e30f;
#pragma unroll
    for (int c = 0; c < CO; c++) {
        v[c] = g_sums[g * CO + c] * inv;
        mx = fmaxf(mx, v[c]);
    }
    float s = 0.f;
#pragma unroll
    for (int c = 0; c < CO; c++) s += __expf(v[c] - mx);
    float lse = logf(s) + mx;
#pragma unroll
    for (int c = 0; c < CO; c++) out[g * CO + c] = v[c] - lse;
}

// ---------------- launcher ---------------------------------------------------
extern "C" void kernel_launch(void* const* d_in, const int* in_sizes, int n_in,
                              void* d_out, int out_size) {
    const float* x        = (const float*)d_in[0];
    const int*   ei       = (const int*)d_in[1];
    const int*   batch    = (const int*)d_in[2];
    const float* W1       = (const float*)d_in[3];
    const float* att_src1 = (const float*)d_in[4];
    const float* att_dst1 = (const float*)d_in[5];
    const float* b1       = (const float*)d_in[6];
    const float* W2       = (const float*)d_in[7];
    const float* att_src2 = (const float*)d_in[8];
    const float* att_dst2 = (const float*)d_in[9];
    const float* b2       = (const float*)d_in[10];
    float* out = (float*)d_out;
    const int E = in_sizes[1] / 2;

    k_zero<<<(NN + 255) / 256, 256>>>();
    k_gemm1<<<dim3((NN + BM - 1) / BM, HC / BN), 256>>>(x, W1);
    k_attn1<<<(NN + 7) / 8, 256>>>(att_src1, att_dst1);
    k_hist<<<(E + 255) / 256, 256>>>(ei, E);
    k_scan<<<1, 1024>>>();
    k_scatter<<<(E + 255) / 256, 256>>>(ei, E);
    k_agg1<<<NN, 256>>>(b1);
    k_gemm2<<<(NN + 7) / 8, 256>>>(W2, att_src2, att_dst2);
    k_agg2<<<(NN + 7) / 8, 256>>>(batch, b2);
    k_final<<<1, NG>>>(out);
}

// round 2
// speedup vs baseline: 1.2408x; 1.2408x over previous
#include <cuda_runtime.h>
#include <cuda_bf16.h>

// Problem constants (fixed by the dataset)
#define NN   50000      // nodes
#define EE   800000     // edges (excluding self loops)
#define FIN  128        // input features
#define H1   8          // heads layer 1
#define C1   32         // channels/head layer 1
#define HC   256        // H1*C1
#define CO   10         // out channels layer 2
#define NG   128        // graphs
#define NEG_SLOPE 0.2f

// ---------------- scratch (device globals; no runtime allocation) ----------
__device__ float          g_xh[(size_t)NN * HC];   // layer1 transformed feats (fp32)
__device__ __nv_bfloat16  g_xhb[(size_t)NN * HC];  // bf16 copy for the gather
__device__ float          g_h1[(size_t)NN * HC];   // layer1 output (post elu)
__device__ float g_as1[NN * H1];
__device__ float g_ad1[NN * H1];
__device__ int   g_deg[NN];
__device__ int   g_off[NN + 1];
__device__ int   g_cur[NN];
__device__ int   g_ssrc[EE];            // edge srcs sorted by dst (CSR)
__device__ float g_xh2[NN * CO];
__device__ float g_as2[NN];
__device__ float g_ad2[NN];
__device__ float g_sums[NG * CO];
__device__ float g_cnt[NG];

__device__ __forceinline__ float lrelu(float x) {
    return fmaxf(x, 0.0f) + NEG_SLOPE * fminf(x, 0.0f);
}
__device__ __forceinline__ float elu(float x) {
    return x > 0.0f ? x : (__expf(x) - 1.0f);
}
// packed fp32x2 helpers (sm_103a FFMA2 — only reachable via PTX)
__device__ __forceinline__ unsigned long long dup_f32x2(float a) {
    unsigned long long r;
    asm("mov.b64 %0, {%1, %1};" : "=l"(r) : "f"(a));
    return r;
}
__device__ __forceinline__ void fma_f32x2(unsigned long long& d,
                                          unsigned long long a,
                                          unsigned long long b) {
    asm("fma.rn.f32x2 %0, %1, %2, %0;" : "+l"(d) : "l"(a), "l"(b));
}

// ---------------- 0. zero counters ----------------------------------------
__global__ void k_zero() {
    int i = blockIdx.x * blockDim.x + threadIdx.x;
    if (i < NN) g_deg[i] = 0;
    if (i < NG * CO) g_sums[i] = 0.0f;
    if (i < NG) g_cnt[i] = 0.0f;
}

// ---------------- 1. GEMM1: xh = x @ W1  (50000x128 @ 128x256) -------------
// 128x128 block tile, 8x8 microtile, f32x2 packed accumulators (FFMA2)
#define BM 128
#define BN 128
#define BK 32
__global__ void __launch_bounds__(256, 2) k_gemm1(const float* __restrict__ x,
                                                  const float* __restrict__ W) {
    __shared__ float AsT[BK][BM];   // A transposed: AsT[k][m]
    __shared__ float Bs[BK][BN];
    const int tid = threadIdx.x;
    const int bm = blockIdx.x * BM;
    const int bn = blockIdx.y * BN;
    const int tx = tid & 15;        // n-dir: 16 threads * 8 cols
    const int ty = tid >> 4;        // m-dir: 16 threads * 8 rows

    unsigned long long acc[8][4];
#pragma unroll
    for (int r = 0; r < 8; r++)
#pragma unroll
        for (int c = 0; c < 4; c++) acc[r][c] = 0ULL;

    // A loader: ar = tid % 128 (row within tile), half selects 16-col chunk
    const int ar = tid & 127;
    const int ah = (tid >> 7) * 16;
    // B loader
    const int br = tid >> 3;            // 0..31
    const int bc = (tid & 7) * 16;      // 0..112

    for (int k0 = 0; k0 < FIN; k0 += BK) {
        // load A tile (128 x 32): each thread 16 floats of one row
        {
            const int row = bm + ar;
            float4 v[4];
            if (row < NN) {
                const float4* p = (const float4*)(x + (size_t)row * FIN + k0 + ah);
#pragma unroll
                for (int j = 0; j < 4; j++) v[j] = p[j];
            } else {
#pragma unroll
                for (int j = 0; j < 4; j++) v[j] = make_float4(0.f, 0.f, 0.f, 0.f);
            }
#pragma unroll
            for (int j = 0; j < 4; j++) {
                AsT[ah + 4 * j + 0][ar] = v[j].x;
                AsT[ah + 4 * j + 1][ar] = v[j].y;
                AsT[ah + 4 * j + 2][ar] = v[j].z;
                AsT[ah + 4 * j + 3][ar] = v[j].w;
            }
        }
        // load B tile (32 x 128)
        {
            const float4* q = (const float4*)(W + (size_t)(k0 + br) * HC + bn + bc);
#pragma unroll
            for (int j = 0; j < 4; j++) *(float4*)&Bs[br][bc + 4 * j] = q[j];
        }
        __syncthreads();
#pragma unroll 8
        for (int kk = 0; kk < BK; kk++) {
            float4 a0 = *(const float4*)&AsT[kk][ty * 8];
            float4 a1 = *(const float4*)&AsT[kk][ty * 8 + 4];
            float4 b0 = *(const float4*)&Bs[kk][tx * 8];
            float4 b1 = *(const float4*)&Bs[kk][tx * 8 + 4];
            unsigned long long B[4];
            B[0] = *(unsigned long long*)&b0.x;
            B[1] = *(unsigned long long*)&b0.z;
            B[2] = *(unsigned long long*)&b1.x;
            B[3] = *(unsigned long long*)&b1.z;
            float a[8] = {a0.x, a0.y, a0.z, a0.w, a1.x, a1.y, a1.z, a1.w};
#pragma unroll
            for (int r = 0; r < 8; r++) {
                unsigned long long a2 = dup_f32x2(a[r]);
#pragma unroll
                for (int c = 0; c < 4; c++) fma_f32x2(acc[r][c], a2, B[c]);
            }
        }
        __syncthreads();
    }
#pragma unroll
    for (int r = 0; r < 8; r++) {
        int row = bm + ty * 8 + r;
        if (row < NN) {
            unsigned long long* dst =
                (unsigned long long*)(g_xh + (size_t)row * HC + bn + tx * 8);
#pragma unroll
            for (int c = 0; c < 4; c++) dst[c] = acc[r][c];
        }
    }
}

// ---------------- 2. attention scalars layer1 + bf16 copy ------------------
__global__ void k_attn1(const float* __restrict__ att_src,
                        const float* __restrict__ att_dst) {
    int warp = threadIdx.x >> 5;
    int lane = threadIdx.x & 31;
    int n = blockIdx.x * 8 + warp;
    if (n >= NN) return;
    const float* row = g_xh + (size_t)n * HC;
    __nv_bfloat162* brow = (__nv_bfloat162*)(g_xhb + (size_t)n * HC);
#pragma unroll
    for (int h = 0; h < H1; h++) {
        float v = row[h * C1 + lane];
        // bf16 copy (pairs from even lanes)
        float vhi = __shfl_down_sync(0xffffffffu, v, 1);
        if (!(lane & 1)) brow[h * 16 + (lane >> 1)] = __floats2bfloat162_rn(v, vhi);
        float ps = v * att_src[h * C1 + lane];
        float pd = v * att_dst[h * C1 + lane];
#pragma unroll
        for (int o = 16; o; o >>= 1) {
            ps += __shfl_xor_sync(0xffffffffu, ps, o);
            pd += __shfl_xor_sync(0xffffffffu, pd, o);
        }
        if (lane == 0) {
            g_as1[n * H1 + h] = ps;
            g_ad1[n * H1 + h] = pd;
        }
    }
}

// ---------------- 3/4/5. CSR build ------------------------------------------
__global__ void k_hist(const int* __restrict__ ei, int E) {
    int e = blockIdx.x * blockDim.x + threadIdx.x;
    if (e < E) atomicAdd(&g_deg[ei[E + e]], 1);
}

__global__ void k_scan() {
    const int T = 1024;
    const int per = (NN + T - 1) / T;
    int t = threadIdx.x;
    int b = t * per;
    int local = 0;
    for (int i = 0; i < per; i++) {
        int idx = b + i;
        if (idx < NN) local += g_deg[idx];
    }
    __shared__ int s[T];
    s[t] = local;
    __syncthreads();
    for (int o = 1; o < T; o <<= 1) {
        int v = (t >= o) ? s[t - o] : 0;
        __syncthreads();
        s[t] += v;
        __syncthreads();
    }
    int base = (t > 0) ? s[t - 1] : 0;
    int run = base;
    for (int i = 0; i < per; i++) {
        int idx = b + i;
        if (idx < NN) {
            g_off[idx] = run;
            g_cur[idx] = run;
            run += g_deg[idx];
        }
    }
    if (t == T - 1) g_off[NN] = s[T - 1];
}

__global__ void k_scatter(const int* __restrict__ ei, int E) {
    int e = blockIdx.x * blockDim.x + threadIdx.x;
    if (e < E) {
        int d = ei[E + e];
        int p = atomicAdd(&g_cur[d], 1);
        g_ssrc[p] = ei[e];
    }
}

// ---------------- 6. layer-1 aggregation: SINGLE-PASS softmax gather --------
// one block (128 thr) per node; warp w = heads {2w, 2w+1}; lane: 2 channels
__global__ void k_agg1(const float* __restrict__ b1) {
    int n = blockIdx.x;
    int w = threadIdx.x >> 5;
    int lane = threadIdx.x & 31;
    int h = w * 2 + (lane >> 4);
    int i = lane & 15;              // channel pair index within head
    const size_t pidx = (size_t)h * 16 + i;

    float ad = g_ad1[n * H1 + h];
    // self loop
    float ws = __expf(lrelu(g_as1[n * H1 + h] + ad));
    float wsum = ws;
    float2 xv = __bfloat1622float2(
        ((const __nv_bfloat162*)(g_xhb + (size_t)n * HC))[pidx]);
    float2 acc = make_float2(ws * xv.x, ws * xv.y);

    int beg = g_off[n], end = g_off[n + 1];
    for (int e = beg; e < end; e++) {
        int s = g_ssrc[e];
        float we = __expf(lrelu(g_as1[s * H1 + h] + ad));
        wsum += we;
        float2 f = __bfloat1622float2(
            ((const __nv_bfloat162*)(g_xhb + (size_t)s * HC))[pidx]);
        acc.x = fmaf(we, f.x, acc.x);
        acc.y = fmaf(we, f.y, acc.y);
    }
    float inv = 1.0f / wsum;
    int c0 = h * C1 + 2 * i;
    float2 o;
    o.x = elu(acc.x * inv + b1[c0]);
    o.y = elu(acc.y * inv + b1[c0 + 1]);
    *(float2*)(g_h1 + (size_t)n * HC + c0) = o;
}

// ---------------- 7. layer-2 GEMV + attention scalars ------------------------
__global__ void k_gemm2(const float* __restrict__ W2,
                        const float* __restrict__ att_src2,
                        const float* __restrict__ att_dst2) {
    int warp = threadIdx.x >> 5;
    int lane = threadIdx.x & 31;
    int n = blockIdx.x * 8 + warp;
    if (n >= NN) return;
    float hreg[8];
    const float* row = g_h1 + (size_t)n * HC;
#pragma unroll
    for (int j = 0; j < 8; j++) hreg[j] = row[j * 32 + lane];
    float a_s = 0.f, a_d = 0.f;
#pragma unroll
    for (int c = 0; c < CO; c++) {
        float p = 0.f;
#pragma unroll
        for (int j = 0; j < 8; j++) p = fmaf(hreg[j], W2[(j * 32 + lane) * CO + c], p);
#pragma unroll
        for (int o = 16; o; o >>= 1) p += __shfl_xor_sync(0xffffffffu, p, o);
        if (lane == 0) {
            g_xh2[n * CO + c] = p;
            a_s = fmaf(p, att_src2[c], a_s);
            a_d = fmaf(p, att_dst2[c], a_d);
        }
    }
    if (lane == 0) {
        g_as2[n] = a_s;
        g_ad2[n] = a_d;
    }
}

// ---------------- 8. layer-2 aggregation (single pass) + pooled atomics ------
__global__ void k_agg2(const int* __restrict__ batch, const float* __restrict__ b2) {
    int warp = threadIdx.x >> 5;
    int lane = threadIdx.x & 31;
    int n = blockIdx.x * 8 + warp;
    if (n >= NN) return;
    float ad = g_ad2[n];
    int beg = g_off[n], end = g_off[n + 1];
    float w = __expf(lrelu(g_as2[n] + ad));
    float wsum = w;
    float acc = (lane < CO) ? w * g_xh2[n * CO + lane] : 0.f;
    for (int e = beg; e < end; e++) {
        int s = g_ssrc[e];
        float we = __expf(lrelu(g_as2[s] + ad));
        wsum += we;
        if (lane < CO) acc = fmaf(we, g_xh2[s * CO + lane], acc);
    }
    if (lane < CO) {
        float out = elu(acc / wsum + b2[lane]);
        atomicAdd(&g_sums[batch[n] * CO + lane], out);
    }
    if (lane == 0) atomicAdd(&g_cnt[batch[n]], 1.0f);
}

// ---------------- 9. mean + log_softmax -------------------------------------
__global__ void k_final(float* __restrict__ out) {
    int g = threadIdx.x;
    if (g >= NG) return;
    float inv = 1.0f / fmaxf(g_cnt[g], 1.0f);
    float v[CO];
    float mx = -1e30f;
#pragma unroll
    for (int c = 0; c < CO; c++) {
        v[c] = g_sums[g * CO + c] * inv;
        mx = fmaxf(mx, v[c]);
    }
    float s = 0.f;
#pragma unroll
    for (int c = 0; c < CO; c++) s += __expf(v[c] - mx);
    float lse = logf(s) + mx;
#pragma unroll
    for (int c = 0; c < CO; c++) out[g * CO + c] = v[c] - lse;
}

// ---------------- launcher ---------------------------------------------------
extern "C" void kernel_launch(void* const* d_in, const int* in_sizes, int n_in,
                              void* d_out, int out_size) {
    const float* x        = (const float*)d_in[0];
    const int*   ei       = (const int*)d_in[1];
    const int*   batch    = (const int*)d_in[2];
    const float* W1       = (const float*)d_in[3];
    const float* att_src1 = (const float*)d_in[4];
    const float* att_dst1 = (const float*)d_in[5];
    const float* b1       = (const float*)d_in[6];
    const float* W2       = (const float*)d_in[7];
    const float* att_src2 = (const float*)d_in[8];
    const float* att_dst2 = (const float*)d_in[9];
    const float* b2       = (const float*)d_in[10];
    float* out = (float*)d_out;
    const int E = in_sizes[1] / 2;

    k_zero<<<(NN + 255) / 256, 256>>>();
    k_gemm1<<<dim3((NN + BM - 1) / BM, HC / BN), 256>>>(x, W1);
    k_attn1<<<(NN + 7) / 8, 256>>>(att_src1, att_dst1);
    k_hist<<<(E + 255) / 256, 256>>>(ei, E);
    k_scan<<<1, 1024>>>();
    k_scatter<<<(E + 255) / 256, 256>>>(ei, E);
    k_agg1<<<NN, 128>>>(b1);
    k_gemm2<<<(NN + 7) / 8, 256>>>(W2, att_src2, att_dst2);
    k_agg2<<<(NN + 7) / 8, 256>>>(batch, b2);
    k_final<<<1, NG>>>(out);
}

// round 3
// speedup vs baseline: 1.4262x; 1.1494x over previous
#include <cuda_runtime.h>
#include <cuda_bf16.h>

// Problem constants (fixed by the dataset)
#define NN   50000      // nodes
#define EE   800000     // edges (excluding self loops)
#define FIN  128        // input features
#define H1   8          // heads layer 1
#define C1   32         // channels/head layer 1
#define HC   256        // H1*C1
#define CO   10         // out channels layer 2
#define NG   128        // graphs
#define NEG_SLOPE 0.2f

// ---------------- scratch (device globals; no runtime allocation) ----------
__device__ __nv_bfloat16  g_xhb[(size_t)NN * HC];  // layer1 feats (bf16)
__device__ __nv_bfloat16  g_h1b[(size_t)NN * HC];  // layer1 output post-elu (bf16)
__device__ float g_as1[NN * H1];
__device__ float g_ad1[NN * H1];
__device__ int   g_deg[NN];
__device__ int   g_off[NN + 1];
__device__ int   g_cur[NN];
__device__ int   g_ssrc[EE];            // edge srcs sorted by dst (CSR)
__device__ float g_xh2[NN * CO];
__device__ float g_as2[NN];
__device__ float g_ad2[NN];
__device__ float g_sums[NG * CO];
__device__ float g_cnt[NG];

__device__ __forceinline__ float lrelu(float x) {
    return fmaxf(x, 0.0f) + NEG_SLOPE * fminf(x, 0.0f);
}
__device__ __forceinline__ float elu(float x) {
    return x > 0.0f ? x : (__expf(x) - 1.0f);
}
// packed fp32x2 helpers (sm_103a FFMA2 — only reachable via PTX)
__device__ __forceinline__ unsigned long long dup_f32x2(float a) {
    unsigned long long r;
    asm("mov.b64 %0, {%1, %1};" : "=l"(r) : "f"(a));
    return r;
}
__device__ __forceinline__ void fma_f32x2(unsigned long long& d,
                                          unsigned long long a,
                                          unsigned long long b) {
    asm("fma.rn.f32x2 %0, %1, %2, %0;" : "+l"(d) : "l"(a), "l"(b));
}
__device__ __forceinline__ void unpack2(unsigned long long p, float& lo, float& hi) {
    asm("mov.b64 {%0, %1}, %2;" : "=f"(lo), "=f"(hi) : "l"(p));
}

// ---------------- 0. zero counters ----------------------------------------
__global__ void k_zero() {
    int i = blockIdx.x * blockDim.x + threadIdx.x;
    if (i < NN) g_deg[i] = 0;
    if (i < NG * CO) g_sums[i] = 0.0f;
    if (i < NG) g_cnt[i] = 0.0f;
}

// ---------------- GEMM1: xh = x @ W1 (50000x128 @ 128x256) + fused attn ----
// 128x128 block tile, 8x8 microtile, f32x2 packed accumulators (FFMA2).
// Epilogue: store bf16 xh, and reduce a_src/a_dst per (row, head) in-warp.
#define BM 128
#define BN 128
#define BK 32
__global__ void __launch_bounds__(256, 2) k_gemm1(const float* __restrict__ x,
                                                  const float* __restrict__ W,
                                                  const float* __restrict__ att_src,
                                                  const float* __restrict__ att_dst) {
    __shared__ float AsT[BK][BM];   // A transposed: AsT[k][m]
    __shared__ float Bs[BK][BN];
    const int tid = threadIdx.x;
    const int bm = blockIdx.x * BM;
    const int bn = blockIdx.y * BN;
    const int tx = tid & 15;        // n-dir: 16 threads * 8 cols
    const int ty = tid >> 4;        // m-dir: 16 threads * 8 rows

    unsigned long long acc[8][4];
#pragma unroll
    for (int r = 0; r < 8; r++)
#pragma unroll
        for (int c = 0; c < 4; c++) acc[r][c] = 0ULL;

    const int ar = tid & 127;           // A loader: row within tile
    const int ah = (tid >> 7) * 16;     // 16-col chunk
    const int br = tid >> 3;            // B loader: 0..31
    const int bc = (tid & 7) * 16;      // 0..112

    for (int k0 = 0; k0 < FIN; k0 += BK) {
        {
            const int row = bm + ar;
            float4 v[4];
            if (row < NN) {
                const float4* p = (const float4*)(x + (size_t)row * FIN + k0 + ah);
#pragma unroll
                for (int j = 0; j < 4; j++) v[j] = p[j];
            } else {
#pragma unroll
                for (int j = 0; j < 4; j++) v[j] = make_float4(0.f, 0.f, 0.f, 0.f);
            }
#pragma unroll
            for (int j = 0; j < 4; j++) {
                AsT[ah + 4 * j + 0][ar] = v[j].x;
                AsT[ah + 4 * j + 1][ar] = v[j].y;
                AsT[ah + 4 * j + 2][ar] = v[j].z;
                AsT[ah + 4 * j + 3][ar] = v[j].w;
            }
        }
        {
            const float4* q = (const float4*)(W + (size_t)(k0 + br) * HC + bn + bc);
#pragma unroll
            for (int j = 0; j < 4; j++) *(float4*)&Bs[br][bc + 4 * j] = q[j];
        }
        __syncthreads();
#pragma unroll 8
        for (int kk = 0; kk < BK; kk++) {
            float4 a0 = *(const float4*)&AsT[kk][ty * 8];
            float4 a1 = *(const float4*)&AsT[kk][ty * 8 + 4];
            float4 b0 = *(const float4*)&Bs[kk][tx * 8];
            float4 b1 = *(const float4*)&Bs[kk][tx * 8 + 4];
            unsigned long long B[4];
            B[0] = *(unsigned long long*)&b0.x;
            B[1] = *(unsigned long long*)&b0.z;
            B[2] = *(unsigned long long*)&b1.x;
            B[3] = *(unsigned long long*)&b1.z;
            float a[8] = {a0.x, a0.y, a0.z, a0.w, a1.x, a1.y, a1.z, a1.w};
#pragma unroll
            for (int r = 0; r < 8; r++) {
                unsigned long long a2 = dup_f32x2(a[r]);
#pragma unroll
                for (int c = 0; c < 4; c++) fma_f32x2(acc[r][c], a2, B[c]);
            }
        }
        __syncthreads();
    }

    // ---- fused epilogue ----
    const int colbase = bn + tx * 8;
    const int head = colbase >> 5;             // 0..7
    float asv[8], adv[8];
#pragma unroll
    for (int j = 0; j < 8; j++) {
        asv[j] = att_src[colbase + j];
        adv[j] = att_dst[colbase + j];
    }
#pragma unroll
    for (int r = 0; r < 8; r++) {
        const int row = bm + ty * 8 + r;
        float f[8];
#pragma unroll
        for (int c = 0; c < 4; c++) unpack2(acc[r][c], f[2 * c], f[2 * c + 1]);
        // bf16 store
        if (row < NN) {
            __nv_bfloat162 b[4];
#pragma unroll
            for (int c = 0; c < 4; c++) b[c] = __floats2bfloat162_rn(f[2 * c], f[2 * c + 1]);
            *(uint4*)(g_xhb + (size_t)row * HC + colbase) = *(uint4*)b;
        }
        // attention partials: reduce 8-col partials across 4 tx-neighbors
        float ps = 0.f, pd = 0.f;
#pragma unroll
        for (int j = 0; j < 8; j++) {
            ps = fmaf(f[j], asv[j], ps);
            pd = fmaf(f[j], adv[j], pd);
        }
        ps += __shfl_xor_sync(0xffffffffu, ps, 1);
        pd += __shfl_xor_sync(0xffffffffu, pd, 1);
        ps += __shfl_xor_sync(0xffffffffu, ps, 2);
        pd += __shfl_xor_sync(0xffffffffu, pd, 2);
        if ((tx & 3) == 0 && row < NN) {
            g_as1[row * H1 + head] = ps;
            g_ad1[row * H1 + head] = pd;
        }
    }
}

// ---------------- CSR build --------------------------------------------------
__global__ void k_hist(const int* __restrict__ ei, int E) {
    int e = blockIdx.x * blockDim.x + threadIdx.x;
    if (e < E) atomicAdd(&g_deg[ei[E + e]], 1);
}

__global__ void k_scan() {
    const int T = 1024;
    const int per = (NN + T - 1) / T;
    int t = threadIdx.x;
    int b = t * per;
    int local = 0;
    for (int i = 0; i < per; i++) {
        int idx = b + i;
        if (idx < NN) local += g_deg[idx];
    }
    __shared__ int s[T];
    s[t] = local;
    __syncthreads();
    for (int o = 1; o < T; o <<= 1) {
        int v = (t >= o) ? s[t - o] : 0;
        __syncthreads();
        s[t] += v;
        __syncthreads();
    }
    int base = (t > 0) ? s[t - 1] : 0;
    int run = base;
    for (int i = 0; i < per; i++) {
        int idx = b + i;
        if (idx < NN) {
            g_off[idx] = run;
            g_cur[idx] = run;
            run += g_deg[idx];
        }
    }
    if (t == T - 1) g_off[NN] = s[T - 1];
}

__global__ void k_scatter(const int* __restrict__ ei, int E) {
    int e = blockIdx.x * blockDim.x + threadIdx.x;
    if (e < E) {
        int d = ei[E + e];
        int p = atomicAdd(&g_cur[d], 1);
        g_ssrc[p] = ei[e];
    }
}

// ---------------- layer-1 aggregation: single-pass softmax gather -----------
// one block (128 thr) per node; warp w = heads {2w, 2w+1}; lane: 2 channels
__global__ void k_agg1(const float* __restrict__ b1) {
    const int n = blockIdx.x;
    const int w = threadIdx.x >> 5;
    const int lane = threadIdx.x & 31;
    const int h = w * 2 + (lane >> 4);
    const int i = lane & 15;
    const size_t pidx = (size_t)h * 16 + i;
    const __nv_bfloat162* xb = (const __nv_bfloat162*)g_xhb;

    const float ad = g_ad1[n * H1 + h];
    // self loop
    float ws = __expf(lrelu(g_as1[n * H1 + h] + ad));
    float wsum = ws;
    float2 xv = __bfloat1622float2(xb[(size_t)n * (HC / 2) + pidx]);
    float2 acc = make_float2(ws * xv.x, ws * xv.y);

    int e = g_off[n];
    const int end = g_off[n + 1];
    for (; e + 4 <= end; e += 4) {
        const int s0 = g_ssrc[e + 0];
        const int s1 = g_ssrc[e + 1];
        const int s2 = g_ssrc[e + 2];
        const int s3 = g_ssrc[e + 3];
        const float a0 = g_as1[s0 * H1 + h];
        const float a1 = g_as1[s1 * H1 + h];
        const float a2 = g_as1[s2 * H1 + h];
        const float a3 = g_as1[s3 * H1 + h];
        const float2 f0 = __bfloat1622float2(xb[(size_t)s0 * (HC / 2) + pidx]);
        const float2 f1 = __bfloat1622float2(xb[(size_t)s1 * (HC / 2) + pidx]);
        const float2 f2 = __bfloat1622float2(xb[(size_t)s2 * (HC / 2) + pidx]);
        const float2 f3 = __bfloat1622float2(xb[(size_t)s3 * (HC / 2) + pidx]);
        const float w0 = __expf(lrelu(a0 + ad));
        const float w1 = __expf(lrelu(a1 + ad));
        const float w2 = __expf(lrelu(a2 + ad));
        const float w3 = __expf(lrelu(a3 + ad));
        wsum += (w0 + w1) + (w2 + w3);
        acc.x = fmaf(w0, f0.x, fmaf(w1, f1.x, fmaf(w2, f2.x, fmaf(w3, f3.x, acc.x))));
        acc.y = fmaf(w0, f0.y, fmaf(w1, f1.y, fmaf(w2, f2.y, fmaf(w3, f3.y, acc.y))));
    }
    for (; e < end; e++) {
        const int s = g_ssrc[e];
        const float we = __expf(lrelu(g_as1[s * H1 + h] + ad));
        wsum += we;
        const float2 f = __bfloat1622float2(xb[(size_t)s * (HC / 2) + pidx]);
        acc.x = fmaf(we, f.x, acc.x);
        acc.y = fmaf(we, f.y, acc.y);
    }
    const float inv = 1.0f / wsum;
    const int c0 = h * C1 + 2 * i;
    const float ox = elu(acc.x * inv + b1[c0]);
    const float oy = elu(acc.y * inv + b1[c0 + 1]);
    ((__nv_bfloat162*)g_h1b)[(size_t)n * (HC / 2) + pidx] = __floats2bfloat162_rn(ox, oy);
}

// ---------------- layer-2 GEMV + attention scalars ----------------------------
__global__ void k_gemm2(const float* __restrict__ W2,
                        const float* __restrict__ att_src2,
                        const float* __restrict__ att_dst2) {
    int warp = threadIdx.x >> 5;
    int lane = threadIdx.x & 31;
    int n = blockIdx.x * 8 + warp;
    if (n >= NN) return;
    float hreg[8];
    const __nv_bfloat16* row = g_h1b + (size_t)n * HC;
#pragma unroll
    for (int j = 0; j < 8; j++) hreg[j] = __bfloat162float(row[j * 32 + lane]);
    float a_s = 0.f, a_d = 0.f;
#pragma unroll
    for (int c = 0; c < CO; c++) {
        float p = 0.f;
#pragma unroll
        for (int j = 0; j < 8; j++) p = fmaf(hreg[j], W2[(j * 32 + lane) * CO + c], p);
#pragma unroll
        for (int o = 16; o; o >>= 1) p += __shfl_xor_sync(0xffffffffu, p, o);
        if (lane == 0) {
            g_xh2[n * CO + c] = p;
            a_s = fmaf(p, att_src2[c], a_s);
            a_d = fmaf(p, att_dst2[c], a_d);
        }
    }
    if (lane == 0) {
        g_as2[n] = a_s;
        g_ad2[n] = a_d;
    }
}

// ---------------- layer-2 aggregation (single pass) + pooled atomics ----------
__global__ void k_agg2(const int* __restrict__ batch, const float* __restrict__ b2) {
    int warp = threadIdx.x >> 5;
    int lane = threadIdx.x & 31;
    int n = blockIdx.x * 8 + warp;
    if (n >= NN) return;
    const float ad = g_ad2[n];
    float w = __expf(lrelu(g_as2[n] + ad));
    float wsum = w;
    float acc = (lane < CO) ? w * g_xh2[n * CO + lane] : 0.f;
    int e = g_off[n];
    const int end = g_off[n + 1];
    for (; e + 4 <= end; e += 4) {
        const int s0 = g_ssrc[e + 0];
        const int s1 = g_ssrc[e + 1];
        const int s2 = g_ssrc[e + 2];
        const int s3 = g_ssrc[e + 3];
        const float w0 = __expf(lrelu(g_as2[s0] + ad));
        const float w1 = __expf(lrelu(g_as2[s1] + ad));
        const float w2 = __expf(lrelu(g_as2[s2] + ad));
        const float w3 = __expf(lrelu(g_as2[s3] + ad));
        float v0 = 0.f, v1 = 0.f, v2 = 0.f, v3 = 0.f;
        if (lane < CO) {
            v0 = g_xh2[s0 * CO + lane];
            v1 = g_xh2[s1 * CO + lane];
            v2 = g_xh2[s2 * CO + lane];
            v3 = g_xh2[s3 * CO + lane];
        }
        wsum += (w0 + w1) + (w2 + w3);
        acc = fmaf(w0, v0, fmaf(w1, v1, fmaf(w2, v2, fmaf(w3, v3, acc))));
    }
    for (; e < end; e++) {
        const int s = g_ssrc[e];
        const float we = __expf(lrelu(g_as2[s] + ad));
        wsum += we;
        if (lane < CO) acc = fmaf(we, g_xh2[s * CO + lane], acc);
    }
    if (lane < CO) {
        float out = elu(acc / wsum + b2[lane]);
        atomicAdd(&g_sums[batch[n] * CO + lane], out);
    }
    if (lane == 0) atomicAdd(&g_cnt[batch[n]], 1.0f);
}

// ---------------- mean + log_softmax ------------------------------------------
__global__ void k_final(float* __restrict__ out) {
    int g = threadIdx.x;
    if (g >= NG) return;
    float inv = 1.0f / fmaxf(g_cnt[g], 1.0f);
    float v[CO];
    float mx = -1e30f;
#pragma unroll
    for (int c = 0; c < CO; c++) {
        v[c] = g_sums[g * CO + c] * inv;
        mx = fmaxf(mx, v[c]);
    }
    float s = 0.f;
#pragma unroll
    for (int c = 0; c < CO; c++) s += __expf(v[c] - mx);
    float lse = logf(s) + mx;
#pragma unroll
    for (int c = 0; c < CO; c++) out[g * CO + c] = v[c] - lse;
}

// ---------------- launcher ------------------------------------------------------
extern "C" void kernel_launch(void* const* d_in, const int* in_sizes, int n_in,
                              void* d_out, int out_size) {
    const float* x        = (const float*)d_in[0];
    const int*   ei       = (const int*)d_in[1];
    const int*   batch    = (const int*)d_in[2];
    const float* W1       = (const float*)d_in[3];
    const float* att_src1 = (const float*)d_in[4];
    const float* att_dst1 = (const float*)d_in[5];
    const float* b1       = (const float*)d_in[6];
    const float* W2       = (const float*)d_in[7];
    const float* att_src2 = (const float*)d_in[8];
    const float* att_dst2 = (const float*)d_in[9];
    const float* b2       = (const float*)d_in[10];
    float* out = (float*)d_out;
    const int E = in_sizes[1] / 2;

    // order chosen so k_gemm1 sits at launch index 3 (ncu -s5 capture slot)
    k_zero<<<(NN + 255) / 256, 256>>>();
    k_hist<<<(E + 255) / 256, 256>>>(ei, E);
    k_scan<<<1, 1024>>>();
    k_gemm1<<<dim3((NN + BM - 1) / BM, HC / BN), 256>>>(x, W1, att_src1, att_dst1);
    k_scatter<<<(E + 255) / 256, 256>>>(ei, E);
    k_agg1<<<NN, 128>>>(b1);
    k_gemm2<<<(NN + 7) / 8, 256>>>(W2, att_src2, att_dst2);
    k_agg2<<<(NN + 7) / 8, 256>>>(batch, b2);
    k_final<<<1, NG>>>(out);
}

// round 5
// speedup vs baseline: 2.2635x; 1.5871x over previous
#include <cuda_runtime.h>
#include <cuda_bf16.h>
#include <cstdint>

// Problem constants (fixed by the dataset)
#define NN   50000
#define EE   800000
#define FIN  128
#define H1   8
#define C1   32
#define HC   256
#define CO   10
#define NG   128
#define NEG_SLOPE 0.2f
#define NBLK 196          // ceil(NN/256)

// ---------------- scratch ----------------------------------------------------
__device__ __nv_bfloat16  g_xhb[(size_t)NN * HC];   // layer1 feats (bf16)
__device__ __nv_bfloat16  g_h1b[(size_t)NN * HC];   // layer1 out post-elu (bf16)
__device__ __nv_bfloat16  g_w1b[(size_t)HC * FIN];  // W1 transposed [n][k] bf16
__device__ float g_as1[NN * H1];
__device__ float g_ad1[NN * H1];
__device__ int   g_deg[NN];
__device__ int   g_off[NN + 1];
__device__ int   g_cur[NN];
__device__ int   g_part[NBLK];
__device__ int   g_ssrc[EE];
__device__ float g_xh2[NN * CO];
__device__ float g_as2[NN];
__device__ float g_ad2[NN];
__device__ float g_sums[NG * CO];
__device__ float g_cnt[NG];

__device__ __forceinline__ float lrelu(float x) {
    return fmaxf(x, 0.0f) + NEG_SLOPE * fminf(x, 0.0f);
}
__device__ __forceinline__ float elu(float x) {
    return x > 0.0f ? x : (__expf(x) - 1.0f);
}

// ---------------- 0. zero ----------------------------------------------------
__global__ void k_zero() {
    int i = blockIdx.x * blockDim.x + threadIdx.x;
    if (i < NN) g_deg[i] = 0;
    if (i < NG * CO) g_sums[i] = 0.0f;
    if (i < NG) g_cnt[i] = 0.0f;
}

// ---------------- W1 transpose+convert: [K][N] fp32 -> [N][K] bf16 -----------
// tiled smem transpose, coalesced on both sides
__global__ void k_cvt_w(const float* __restrict__ W1) {
    __shared__ float s[32][33];
    int k0 = blockIdx.x * 32;     // K tiles: 128/32 = 4
    int n0 = blockIdx.y * 32;     // N tiles: 256/32 = 8
    int tx = threadIdx.x, ty = threadIdx.y;
    s[ty][tx] = W1[(size_t)(k0 + ty) * HC + n0 + tx];
    __syncthreads();
    g_w1b[(size_t)(n0 + ty) * FIN + k0 + tx] = __float2bfloat16(s[tx][ty]);
}

// ---------------- GEMM1 via mma.sync HMMA: CTA tile 64x256, K=128 -------------
// smem: A [64][136] bf16 (17408 B) then B [256][136] bf16 (69632 B)
#define G1_ST   136                    // padded row stride (bf16 elems)
#define G1_ASZ  (64 * G1_ST * 2)
#define G1_SMEM (G1_ASZ + 256 * G1_ST * 2)

__device__ __forceinline__ void mma16816(float* d, const uint32_t* a, const uint32_t* b) {
    asm volatile(
        "mma.sync.aligned.m16n8k16.row.col.f32.bf16.bf16.f32 "
        "{%0,%1,%2,%3}, {%4,%5,%6,%7}, {%8,%9}, {%0,%1,%2,%3};"
        : "+f"(d[0]), "+f"(d[1]), "+f"(d[2]), "+f"(d[3])
        : "r"(a[0]), "r"(a[1]), "r"(a[2]), "r"(a[3]), "r"(b[0]), "r"(b[1]));
}

__global__ void __launch_bounds__(256, 1) k_gemm1(const float* __restrict__ x,
                                                  const float* __restrict__ att_src,
                                                  const float* __restrict__ att_dst) {
    extern __shared__ char smem[];
    char* sA = smem;
    char* sB = smem + G1_ASZ;
    const int tid = threadIdx.x;
    const int wid = tid >> 5;
    const int lane = tid & 31;
    const int bm = blockIdx.x * 64;
    const int mw = wid >> 2;          // 0..1   (m warp)
    const int nw = wid & 3;           // 0..3   (n warp)
    const int g = lane >> 2;          // 0..7
    const int t2 = (lane & 3) * 2;    // 0,2,4,6

    // ---- load A: 64 rows of x -> bf16, row-major stride 136 ----
#pragma unroll
    for (int i = 0; i < 8; i++) {
        int idx = tid + i * 256;              // 0..2047
        int row = idx >> 5;
        int c4 = idx & 31;                    // float4 index
        float4 v = make_float4(0.f, 0.f, 0.f, 0.f);
        int grow = bm + row;
        if (grow < NN) v = *(const float4*)(x + (size_t)grow * FIN + c4 * 4);
        __nv_bfloat162 b0 = __floats2bfloat162_rn(v.x, v.y);
        __nv_bfloat162 b1 = __floats2bfloat162_rn(v.z, v.w);
        uint2 p = make_uint2(*(uint32_t*)&b0, *(uint32_t*)&b1);
        *(uint2*)(sA + row * (G1_ST * 2) + c4 * 8) = p;
    }
    // ---- load B: g_w1b [256][128] bf16, stride 136 ----
#pragma unroll
    for (int i = 0; i < 16; i++) {
        int idx = tid + i * 256;              // 0..4095
        int row = idx >> 4;
        int c16 = idx & 15;                   // uint4 index (8 bf16)
        uint4 v = *(const uint4*)(g_w1b + (size_t)row * FIN + c16 * 8);
        *(uint4*)(sB + row * (G1_ST * 2) + c16 * 16) = v;
    }
    __syncthreads();

    // ---- main MMA loops ----
    float acc[2][8][4];
#pragma unroll
    for (int mt = 0; mt < 2; mt++)
#pragma unroll
        for (int j = 0; j < 8; j++)
#pragma unroll
            for (int q = 0; q < 4; q++) acc[mt][j][q] = 0.f;

#pragma unroll
    for (int kk = 0; kk < 8; kk++) {
        const int k0 = kk * 16;
        uint32_t afr[2][4];
#pragma unroll
        for (int mt = 0; mt < 2; mt++) {
            int rb = mw * 32 + mt * 16;
            afr[mt][0] = *(const uint32_t*)(sA + (rb + g) * (G1_ST * 2) + (k0 + t2) * 2);
            afr[mt][1] = *(const uint32_t*)(sA + (rb + g + 8) * (G1_ST * 2) + (k0 + t2) * 2);
            afr[mt][2] = *(const uint32_t*)(sA + (rb + g) * (G1_ST * 2) + (k0 + 8 + t2) * 2);
            afr[mt][3] = *(const uint32_t*)(sA + (rb + g + 8) * (G1_ST * 2) + (k0 + 8 + t2) * 2);
        }
        uint32_t bfr[8][2];
#pragma unroll
        for (int j = 0; j < 8; j++) {
            int nb = nw * 64 + j * 8 + g;
            bfr[j][0] = *(const uint32_t*)(sB + nb * (G1_ST * 2) + (k0 + t2) * 2);
            bfr[j][1] = *(const uint32_t*)(sB + nb * (G1_ST * 2) + (k0 + 8 + t2) * 2);
        }
#pragma unroll
        for (int mt = 0; mt < 2; mt++)
#pragma unroll
            for (int j = 0; j < 8; j++) mma16816(acc[mt][j], afr[mt], bfr[j]);
    }

    // ---- fused epilogue: bf16 store + attention logits ----
#pragma unroll
    for (int mt = 0; mt < 2; mt++) {
        const int r0 = bm + mw * 32 + mt * 16 + g;
        const int r1 = r0 + 8;
        // bf16 stores
#pragma unroll
        for (int j = 0; j < 8; j++) {
            const int c = nw * 64 + j * 8 + t2;
            __nv_bfloat162 v0 = __floats2bfloat162_rn(acc[mt][j][0], acc[mt][j][1]);
            __nv_bfloat162 v1 = __floats2bfloat162_rn(acc[mt][j][2], acc[mt][j][3]);
            if (r0 < NN) *(uint32_t*)(g_xhb + (size_t)r0 * HC + c) = *(uint32_t*)&v0;
            if (r1 < NN) *(uint32_t*)(g_xhb + (size_t)r1 * HC + c) = *(uint32_t*)&v1;
        }
        // attention partials: 2 heads per warp n-span
#pragma unroll
        for (int hh = 0; hh < 2; hh++) {
            float ps0 = 0.f, pd0 = 0.f, ps1 = 0.f, pd1 = 0.f;
#pragma unroll
            for (int jj = 0; jj < 4; jj++) {
                const int j = hh * 4 + jj;
                const int c = nw * 64 + j * 8 + t2;
                float2 s2 = *(const float2*)(att_src + c);
                float2 d2 = *(const float2*)(att_dst + c);
                ps0 = fmaf(acc[mt][j][0], s2.x, fmaf(acc[mt][j][1], s2.y, ps0));
                pd0 = fmaf(acc[mt][j][0], d2.x, fmaf(acc[mt][j][1], d2.y, pd0));
                ps1 = fmaf(acc[mt][j][2], s2.x, fmaf(acc[mt][j][3], s2.y, ps1));
                pd1 = fmaf(acc[mt][j][2], d2.x, fmaf(acc[mt][j][3], d2.y, pd1));
            }
            ps0 += __shfl_xor_sync(0xffffffffu, ps0, 1);
            pd0 += __shfl_xor_sync(0xffffffffu, pd0, 1);
            ps1 += __shfl_xor_sync(0xffffffffu, ps1, 1);
            pd1 += __shfl_xor_sync(0xffffffffu, pd1, 1);
            ps0 += __shfl_xor_sync(0xffffffffu, ps0, 2);
            pd0 += __shfl_xor_sync(0xffffffffu, pd0, 2);
            ps1 += __shfl_xor_sync(0xffffffffu, ps1, 2);
            pd1 += __shfl_xor_sync(0xffffffffu, pd1, 2);
            const int h = nw * 2 + hh;
            if ((lane & 3) == 0) {
                if (r0 < NN) { g_as1[r0 * H1 + h] = ps0; g_ad1[r0 * H1 + h] = pd0; }
                if (r1 < NN) { g_as1[r1 * H1 + h] = ps1; g_ad1[r1 * H1 + h] = pd1; }
            }
        }
    }
}

// ---------------- CSR build ----------------------------------------------------
__global__ void k_hist(const int* __restrict__ ei, int E) {
    int e = blockIdx.x * blockDim.x + threadIdx.x;
    if (e < E) atomicAdd(&g_deg[ei[E + e]], 1);
}

__global__ void k_scan1() {
    __shared__ int s[256];
    int i = blockIdx.x * 256 + threadIdx.x;
    int v = (i < NN) ? g_deg[i] : 0;
    s[threadIdx.x] = v;
    __syncthreads();
    for (int o = 128; o; o >>= 1) {
        if (threadIdx.x < o) s[threadIdx.x] += s[threadIdx.x + o];
        __syncthreads();
    }
    if (threadIdx.x == 0) g_part[blockIdx.x] = s[0];
}

__global__ void k_scan2() {
    __shared__ int s[256];
    int t = threadIdx.x;
    int v = (t < NBLK) ? g_part[t] : 0;
    s[t] = v;
    __syncthreads();
    for (int o = 1; o < 256; o <<= 1) {
        int u = (t >= o) ? s[t - o] : 0;
        __syncthreads();
        s[t] += u;
        __syncthreads();
    }
    if (t < NBLK) g_part[t] = s[t] - v;   // exclusive
}

__global__ void k_scan3() {
    __shared__ int s[256];
    int t = threadIdx.x;
    int i = blockIdx.x * 256 + t;
    int v = (i < NN) ? g_deg[i] : 0;
    s[t] = v;
    __syncthreads();
    for (int o = 1; o < 256; o <<= 1) {
        int u = (t >= o) ? s[t - o] : 0;
        __syncthreads();
        s[t] += u;
        __syncthreads();
    }
    int base = g_part[blockIdx.x];
    if (i < NN) {
        int off = base + s[t] - v;
        g_off[i] = off;
        g_cur[i] = off;
        if (i == NN - 1) g_off[NN] = base + s[t];
    }
}

__global__ void k_scatter(const int* __restrict__ ei, int E) {
    int e = blockIdx.x * blockDim.x + threadIdx.x;
    if (e < E) {
        int d = ei[E + e];
        int p = atomicAdd(&g_cur[d], 1);
        g_ssrc[p] = ei[e];
    }
}

// ---------------- layer-1 aggregation ------------------------------------------
__global__ void k_agg1(const float* __restrict__ b1) {
    const int n = blockIdx.x;
    const int w = threadIdx.x >> 5;
    const int lane = threadIdx.x & 31;
    const int h = w * 2 + (lane >> 4);
    const int i = lane & 15;
    const size_t pidx = (size_t)h * 16 + i;
    const __nv_bfloat162* xb = (const __nv_bfloat162*)g_xhb;

    const float ad = g_ad1[n * H1 + h];
    float ws = __expf(lrelu(g_as1[n * H1 + h] + ad));
    float wsum = ws;
    float2 xv = __bfloat1622float2(xb[(size_t)n * (HC / 2) + pidx]);
    float2 acc = make_float2(ws * xv.x, ws * xv.y);

    int e = g_off[n];
    const int end = g_off[n + 1];
    for (; e + 4 <= end; e += 4) {
        const int s0 = g_ssrc[e + 0], s1 = g_ssrc[e + 1];
        const int s2 = g_ssrc[e + 2], s3 = g_ssrc[e + 3];
        const float a0 = g_as1[s0 * H1 + h], a1 = g_as1[s1 * H1 + h];
        const float a2 = g_as1[s2 * H1 + h], a3 = g_as1[s3 * H1 + h];
        const float2 f0 = __bfloat1622float2(xb[(size_t)s0 * (HC / 2) + pidx]);
        const float2 f1 = __bfloat1622float2(xb[(size_t)s1 * (HC / 2) + pidx]);
        const float2 f2 = __bfloat1622float2(xb[(size_t)s2 * (HC / 2) + pidx]);
        const float2 f3 = __bfloat1622float2(xb[(size_t)s3 * (HC / 2) + pidx]);
        const float w0 = __expf(lrelu(a0 + ad)), w1 = __expf(lrelu(a1 + ad));
        const float w2 = __expf(lrelu(a2 + ad)), w3 = __expf(lrelu(a3 + ad));
        wsum += (w0 + w1) + (w2 + w3);
        acc.x = fmaf(w0, f0.x, fmaf(w1, f1.x, fmaf(w2, f2.x, fmaf(w3, f3.x, acc.x))));
        acc.y = fmaf(w0, f0.y, fmaf(w1, f1.y, fmaf(w2, f2.y, fmaf(w3, f3.y, acc.y))));
    }
    for (; e < end; e++) {
        const int s = g_ssrc[e];
        const float we = __expf(lrelu(g_as1[s * H1 + h] + ad));
        wsum += we;
        const float2 f = __bfloat1622float2(xb[(size_t)s * (HC / 2) + pidx]);
        acc.x = fmaf(we, f.x, acc.x);
        acc.y = fmaf(we, f.y, acc.y);
    }
    const float inv = 1.0f / wsum;
    const int c0 = h * C1 + 2 * i;
    const float ox = elu(acc.x * inv + b1[c0]);
    const float oy = elu(acc.y * inv + b1[c0 + 1]);
    ((__nv_bfloat162*)g_h1b)[(size_t)n * (HC / 2) + pidx] = __floats2bfloat162_rn(ox, oy);
}

// ---------------- layer-2 GEMV + attention scalars (W2 in smem) -----------------
__global__ void k_gemm2(const float* __restrict__ W2,
                        const float* __restrict__ att_src2,
                        const float* __restrict__ att_dst2) {
    __shared__ float sW2[HC * CO];
    for (int i = threadIdx.x; i < HC * CO; i += 256) sW2[i] = W2[i];
    __syncthreads();
    int warp = threadIdx.x >> 5;
    int lane = threadIdx.x & 31;
    int n = blockIdx.x * 8 + warp;
    if (n >= NN) return;
    float hreg[8];
    const __nv_bfloat16* row = g_h1b + (size_t)n * HC;
#pragma unroll
    for (int j = 0; j < 8; j++) hreg[j] = __bfloat162float(row[j * 32 + lane]);
    float a_s = 0.f, a_d = 0.f;
#pragma unroll
    for (int c = 0; c < CO; c++) {
        float p = 0.f;
#pragma unroll
        for (int j = 0; j < 8; j++) p = fmaf(hreg[j], sW2[(j * 32 + lane) * CO + c], p);
#pragma unroll
        for (int o = 16; o; o >>= 1) p += __shfl_xor_sync(0xffffffffu, p, o);
        if (lane == 0) {
            g_xh2[n * CO + c] = p;
            a_s = fmaf(p, att_src2[c], a_s);
            a_d = fmaf(p, att_dst2[c], a_d);
        }
    }
    if (lane == 0) {
        g_as2[n] = a_s;
        g_ad2[n] = a_d;
    }
}

// ---------------- layer-2 aggregation + pooled atomics ---------------------------
__global__ void k_agg2(const int* __restrict__ batch, const float* __restrict__ b2) {
    int warp = threadIdx.x >> 5;
    int lane = threadIdx.x & 31;
    int n = blockIdx.x * 8 + warp;
    if (n >= NN) return;
    const float ad = g_ad2[n];
    float w = __expf(lrelu(g_as2[n] + ad));
    float wsum = w;
    float acc = (lane < CO) ? w * g_xh2[n * CO + lane] : 0.f;
    int e = g_off[n];
    const int end = g_off[n + 1];
    for (; e + 4 <= end; e += 4) {
        const int s0 = g_ssrc[e + 0], s1 = g_ssrc[e + 1];
        const int s2 = g_ssrc[e + 2], s3 = g_ssrc[e + 3];
        const float w0 = __expf(lrelu(g_as2[s0] + ad));
        const float w1 = __expf(lrelu(g_as2[s1] + ad));
        const float w2 = __expf(lrelu(g_as2[s2] + ad));
        const float w3 = __expf(lrelu(g_as2[s3] + ad));
        float v0 = 0.f, v1 = 0.f, v2 = 0.f, v3 = 0.f;
        if (lane < CO) {
            v0 = g_xh2[s0 * CO + lane];
            v1 = g_xh2[s1 * CO + lane];
            v2 = g_xh2[s2 * CO + lane];
            v3 = g_xh2[s3 * CO + lane];
        }
        wsum += (w0 + w1) + (w2 + w3);
        acc = fmaf(w0, v0, fmaf(w1, v1, fmaf(w2, v2, fmaf(w3, v3, acc))));
    }
    for (; e < end; e++) {
        const int s = g_ssrc[e];
        const float we = __expf(lrelu(g_as2[s] + ad));
        wsum += we;
        if (lane < CO) acc = fmaf(we, g_xh2[s * CO + lane], acc);
    }
    if (lane < CO) {
        float out = elu(acc / wsum + b2[lane]);
        atomicAdd(&g_sums[batch[n] * CO + lane], out);
    }
    if (lane == 0) atomicAdd(&g_cnt[batch[n]], 1.0f);
}

// ---------------- mean + log_softmax ----------------------------------------------
__global__ void k_final(float* __restrict__ out) {
    int g = threadIdx.x;
    if (g >= NG) return;
    float inv = 1.0f / fmaxf(g_cnt[g], 1.0f);
    float v[CO];
    float mx = -1e30f;
#pragma unroll
    for (int c = 0; c < CO; c++) {
        v[c] = g_sums[g * CO + c] * inv;
        mx = fmaxf(mx, v[c]);
    }
    float s = 0.f;
#pragma unroll
    for (int c = 0; c < CO; c++) s += __expf(v[c] - mx);
    float lse = logf(s) + mx;
#pragma unroll
    for (int c = 0; c < CO; c++) out[g * CO + c] = v[c] - lse;
}

// ---------------- launcher ----------------------------------------------------------
extern "C" void kernel_launch(void* const* d_in, const int* in_sizes, int n_in,
                              void* d_out, int out_size) {
    const float* x        = (const float*)d_in[0];
    const int*   ei       = (const int*)d_in[1];
    const int*   batch    = (const int*)d_in[2];
    const float* W1       = (const float*)d_in[3];
    const float* att_src1 = (const float*)d_in[4];
    const float* att_dst1 = (const float*)d_in[5];
    const float* b1       = (const float*)d_in[6];
    const float* W2       = (const float*)d_in[7];
    const float* att_src2 = (const float*)d_in[8];
    const float* att_dst2 = (const float*)d_in[9];
    const float* b2       = (const float*)d_in[10];
    float* out = (float*)d_out;
    const int E = in_sizes[1] / 2;

    cudaFuncSetAttribute(k_gemm1, cudaFuncAttributeMaxDynamicSharedMemorySize, G1_SMEM);

    k_zero<<<(NN + 255) / 256, 256>>>();
    k_hist<<<(E + 255) / 256, 256>>>(ei, E);
    k_cvt_w<<<dim3(FIN / 32, HC / 32), dim3(32, 32)>>>(W1);
    k_gemm1<<<(NN + 63) / 64, 256, G1_SMEM>>>(x, att_src1, att_dst1);  // profiled slot
    k_scan1<<<NBLK, 256>>>();
    k_scan2<<<1, 256>>>();
    k_scan3<<<NBLK, 256>>>();
    k_scatter<<<(E + 255) / 256, 256>>>(ei, E);
    k_agg1<<<NN, 128>>>(b1);
    k_gemm2<<<(NN + 7) / 8, 256>>>(W2, att_src2, att_dst2);
    k_agg2<<<(NN + 7) / 8, 256>>>(batch, b2);
    k_final<<<1, NG>>>(out);
}

// round 6
// speedup vs baseline: 3.3807x; 1.4936x over previous
#include <cuda_runtime.h>
#include <cuda_bf16.h>
#include <cstdint>

#define NN   50000
#define EE   800000
#define FIN  128
#define H1   8
#define C1   32
#define HC   256
#define CO   10
#define NG   128
#define NEG_SLOPE 0.2f
#define NBLK 196          // ceil(NN/256)

// ---------------- scratch ----------------------------------------------------
__device__ __nv_bfloat16  g_xhb[(size_t)NN * HC];   // layer1 feats (bf16)
__device__ __nv_bfloat16  g_h1b[(size_t)NN * HC];   // layer1 out post-elu (bf16)
__device__ __nv_bfloat16  g_w1b[(size_t)HC * FIN];  // W1 transposed [n][k] bf16
__device__ float g_as1[NN * H1];
__device__ float g_ad1[NN * H1];
__device__ int   g_deg[NN];
__device__ int   g_off[NN + 1];
__device__ int   g_cur[NN];
__device__ int   g_part[NBLK];
__device__ int   g_ssrc[EE];
__device__ float g_xh2[(size_t)NN * 16];   // padded stride 16, cols 10..15 = 0
__device__ float g_as2[NN];
__device__ float g_ad2[NN];
__device__ float g_sums[NG * CO];
__device__ float g_cnt[NG];

__device__ __forceinline__ float lrelu(float x) {
    return fmaxf(x, 0.0f) + NEG_SLOPE * fminf(x, 0.0f);
}
__device__ __forceinline__ float elu(float x) {
    return x > 0.0f ? x : (__expf(x) - 1.0f);
}

__device__ __forceinline__ void mma16816(float* d, const uint32_t* a, const uint32_t* b) {
    asm volatile(
        "mma.sync.aligned.m16n8k16.row.col.f32.bf16.bf16.f32 "
        "{%0,%1,%2,%3}, {%4,%5,%6,%7}, {%8,%9}, {%0,%1,%2,%3};"
        : "+f"(d[0]), "+f"(d[1]), "+f"(d[2]), "+f"(d[3])
        : "r"(a[0]), "r"(a[1]), "r"(a[2]), "r"(a[3]), "r"(b[0]), "r"(b[1]));
}

// ---------------- 0. zero ----------------------------------------------------
__global__ void k_zero() {
    int i = blockIdx.x * blockDim.x + threadIdx.x;
    if (i < NN) g_deg[i] = 0;
    if (i < NG * CO) g_sums[i] = 0.0f;
    if (i < NG) g_cnt[i] = 0.0f;
}

// ---------------- W1 transpose+convert ----------------------------------------
__global__ void k_cvt_w(const float* __restrict__ W1) {
    __shared__ float s[32][33];
    int k0 = blockIdx.x * 32;
    int n0 = blockIdx.y * 32;
    int tx = threadIdx.x, ty = threadIdx.y;
    s[ty][tx] = W1[(size_t)(k0 + ty) * HC + n0 + tx];
    __syncthreads();
    g_w1b[(size_t)(n0 + ty) * FIN + k0 + tx] = __float2bfloat16(s[tx][ty]);
}

// ---------------- GEMM1 HMMA: CTA tile 64x256, K=128 --------------------------
#define G1_ST   136
#define G1_ASZ  (64 * G1_ST * 2)
#define G1_SMEM (G1_ASZ + 256 * G1_ST * 2)
__global__ void __launch_bounds__(256, 2) k_gemm1(const float* __restrict__ x,
                                                  const float* __restrict__ att_src,
                                                  const float* __restrict__ att_dst) {
    extern __shared__ char smem[];
    char* sA = smem;
    char* sB = smem + G1_ASZ;
    const int tid = threadIdx.x;
    const int wid = tid >> 5;
    const int lane = tid & 31;
    const int bm = blockIdx.x * 64;
    const int mw = wid >> 2;
    const int nw = wid & 3;
    const int g = lane >> 2;
    const int t2 = (lane & 3) * 2;

#pragma unroll
    for (int i = 0; i < 8; i++) {
        int idx = tid + i * 256;
        int row = idx >> 5;
        int c4 = idx & 31;
        float4 v = make_float4(0.f, 0.f, 0.f, 0.f);
        int grow = bm + row;
        if (grow < NN) v = *(const float4*)(x + (size_t)grow * FIN + c4 * 4);
        __nv_bfloat162 b0 = __floats2bfloat162_rn(v.x, v.y);
        __nv_bfloat162 b1 = __floats2bfloat162_rn(v.z, v.w);
        uint2 p = make_uint2(*(uint32_t*)&b0, *(uint32_t*)&b1);
        *(uint2*)(sA + row * (G1_ST * 2) + c4 * 8) = p;
    }
#pragma unroll
    for (int i = 0; i < 16; i++) {
        int idx = tid + i * 256;
        int row = idx >> 4;
        int c16 = idx & 15;
        uint4 v = *(const uint4*)(g_w1b + (size_t)row * FIN + c16 * 8);
        *(uint4*)(sB + row * (G1_ST * 2) + c16 * 16) = v;
    }
    __syncthreads();

    float acc[2][8][4];
#pragma unroll
    for (int mt = 0; mt < 2; mt++)
#pragma unroll
        for (int j = 0; j < 8; j++)
#pragma unroll
            for (int q = 0; q < 4; q++) acc[mt][j][q] = 0.f;

#pragma unroll
    for (int kk = 0; kk < 8; kk++) {
        const int k0 = kk * 16;
        uint32_t afr[2][4];
#pragma unroll
        for (int mt = 0; mt < 2; mt++) {
            int rb = mw * 32 + mt * 16;
            afr[mt][0] = *(const uint32_t*)(sA + (rb + g) * (G1_ST * 2) + (k0 + t2) * 2);
            afr[mt][1] = *(const uint32_t*)(sA + (rb + g + 8) * (G1_ST * 2) + (k0 + t2) * 2);
            afr[mt][2] = *(const uint32_t*)(sA + (rb + g) * (G1_ST * 2) + (k0 + 8 + t2) * 2);
            afr[mt][3] = *(const uint32_t*)(sA + (rb + g + 8) * (G1_ST * 2) + (k0 + 8 + t2) * 2);
        }
        uint32_t bfr[8][2];
#pragma unroll
        for (int j = 0; j < 8; j++) {
            int nb = nw * 64 + j * 8 + g;
            bfr[j][0] = *(const uint32_t*)(sB + nb * (G1_ST * 2) + (k0 + t2) * 2);
            bfr[j][1] = *(const uint32_t*)(sB + nb * (G1_ST * 2) + (k0 + 8 + t2) * 2);
        }
#pragma unroll
        for (int mt = 0; mt < 2; mt++)
#pragma unroll
            for (int j = 0; j < 8; j++) mma16816(acc[mt][j], afr[mt], bfr[j]);
    }

#pragma unroll
    for (int mt = 0; mt < 2; mt++) {
        const int r0 = bm + mw * 32 + mt * 16 + g;
        const int r1 = r0 + 8;
#pragma unroll
        for (int j = 0; j < 8; j++) {
            const int c = nw * 64 + j * 8 + t2;
            __nv_bfloat162 v0 = __floats2bfloat162_rn(acc[mt][j][0], acc[mt][j][1]);
            __nv_bfloat162 v1 = __floats2bfloat162_rn(acc[mt][j][2], acc[mt][j][3]);
            if (r0 < NN) *(uint32_t*)(g_xhb + (size_t)r0 * HC + c) = *(uint32_t*)&v0;
            if (r1 < NN) *(uint32_t*)(g_xhb + (size_t)r1 * HC + c) = *(uint32_t*)&v1;
        }
#pragma unroll
        for (int hh = 0; hh < 2; hh++) {
            float ps0 = 0.f, pd0 = 0.f, ps1 = 0.f, pd1 = 0.f;
#pragma unroll
            for (int jj = 0; jj < 4; jj++) {
                const int j = hh * 4 + jj;
                const int c = nw * 64 + j * 8 + t2;
                float2 s2 = *(const float2*)(att_src + c);
                float2 d2 = *(const float2*)(att_dst + c);
                ps0 = fmaf(acc[mt][j][0], s2.x, fmaf(acc[mt][j][1], s2.y, ps0));
                pd0 = fmaf(acc[mt][j][0], d2.x, fmaf(acc[mt][j][1], d2.y, pd0));
                ps1 = fmaf(acc[mt][j][2], s2.x, fmaf(acc[mt][j][3], s2.y, ps1));
                pd1 = fmaf(acc[mt][j][2], d2.x, fmaf(acc[mt][j][3], d2.y, pd1));
            }
            ps0 += __shfl_xor_sync(0xffffffffu, ps0, 1);
            pd0 += __shfl_xor_sync(0xffffffffu, pd0, 1);
            ps1 += __shfl_xor_sync(0xffffffffu, ps1, 1);
            pd1 += __shfl_xor_sync(0xffffffffu, pd1, 1);
            ps0 += __shfl_xor_sync(0xffffffffu, ps0, 2);
            pd0 += __shfl_xor_sync(0xffffffffu, pd0, 2);
            ps1 += __shfl_xor_sync(0xffffffffu, ps1, 2);
            pd1 += __shfl_xor_sync(0xffffffffu, pd1, 2);
            const int h = nw * 2 + hh;
            if ((lane & 3) == 0) {
                if (r0 < NN) { g_as1[r0 * H1 + h] = ps0; g_ad1[r0 * H1 + h] = pd0; }
                if (r1 < NN) { g_as1[r1 * H1 + h] = ps1; g_ad1[r1 * H1 + h] = pd1; }
            }
        }
    }
}

// ---------------- CSR build ----------------------------------------------------
__global__ void k_hist(const int* __restrict__ ei, int E) {
    int e = blockIdx.x * blockDim.x + threadIdx.x;
    if (e < E) atomicAdd(&g_deg[ei[E + e]], 1);
}
__global__ void k_scan1() {
    __shared__ int s[256];
    int i = blockIdx.x * 256 + threadIdx.x;
    int v = (i < NN) ? g_deg[i] : 0;
    s[threadIdx.x] = v;
    __syncthreads();
    for (int o = 128; o; o >>= 1) {
        if (threadIdx.x < o) s[threadIdx.x] += s[threadIdx.x + o];
        __syncthreads();
    }
    if (threadIdx.x == 0) g_part[blockIdx.x] = s[0];
}
__global__ void k_scan2() {
    __shared__ int s[256];
    int t = threadIdx.x;
    int v = (t < NBLK) ? g_part[t] : 0;
    s[t] = v;
    __syncthreads();
    for (int o = 1; o < 256; o <<= 1) {
        int u = (t >= o) ? s[t - o] : 0;
        __syncthreads();
        s[t] += u;
        __syncthreads();
    }
    if (t < NBLK) g_part[t] = s[t] - v;
}
__global__ void k_scan3() {
    __shared__ int s[256];
    int t = threadIdx.x;
    int i = blockIdx.x * 256 + t;
    int v = (i < NN) ? g_deg[i] : 0;
    s[t] = v;
    __syncthreads();
    for (int o = 1; o < 256; o <<= 1) {
        int u = (t >= o) ? s[t - o] : 0;
        __syncthreads();
        s[t] += u;
        __syncthreads();
    }
    int base = g_part[blockIdx.x];
    if (i < NN) {
        int off = base + s[t] - v;
        g_off[i] = off;
        g_cur[i] = off;
        if (i == NN - 1) g_off[NN] = base + s[t];
    }
}
__global__ void k_scatter(const int* __restrict__ ei, int E) {
    int e = blockIdx.x * blockDim.x + threadIdx.x;
    if (e < E) {
        int d = ei[E + e];
        int p = atomicAdd(&g_cur[d], 1);
        g_ssrc[p] = ei[e];
    }
}

// ---------------- layer-1 aggregation: warp per node ----------------------------
// lane = head(0..7)*4 + quad(0..3); each lane owns 8 channels (one uint4 of bf16)
__global__ void k_agg1(const float* __restrict__ b1) {
    const int warp = threadIdx.x >> 5;
    const int lane = threadIdx.x & 31;
    const int n = blockIdx.x * 8 + warp;
    if (n >= NN) return;
    const int h = lane >> 2;
    const int q = lane & 3;
    const int vidx = h * 4 + q;                       // uint4 index within row
    const uint4* xb = (const uint4*)g_xhb;            // 32 uint4 per row

    const float ad = g_ad1[n * H1 + h];
    float w = __expf(lrelu(g_as1[n * H1 + h] + ad));
    float wsum = w;
    float acc[8];
    {
        uint4 sv = xb[(size_t)n * 32 + vidx];
        const __nv_bfloat162* bp = (const __nv_bfloat162*)&sv;
#pragma unroll
        for (int j = 0; j < 4; j++) {
            float2 f = __bfloat1622float2(bp[j]);
            acc[2 * j] = w * f.x;
            acc[2 * j + 1] = w * f.y;
        }
    }
    int e = g_off[n];
    const int end = g_off[n + 1];
    for (; e + 2 <= end; e += 2) {
        const int s0 = g_ssrc[e];
        const int s1 = g_ssrc[e + 1];
        const float a0 = g_as1[s0 * H1 + h];
        const float a1 = g_as1[s1 * H1 + h];
        const uint4 v0 = xb[(size_t)s0 * 32 + vidx];
        const uint4 v1 = xb[(size_t)s1 * 32 + vidx];
        const float w0 = __expf(lrelu(a0 + ad));
        const float w1 = __expf(lrelu(a1 + ad));
        wsum += w0 + w1;
        const __nv_bfloat162* p0 = (const __nv_bfloat162*)&v0;
        const __nv_bfloat162* p1 = (const __nv_bfloat162*)&v1;
#pragma unroll
        for (int j = 0; j < 4; j++) {
            float2 f0 = __bfloat1622float2(p0[j]);
            float2 f1 = __bfloat1622float2(p1[j]);
            acc[2 * j]     = fmaf(w0, f0.x, fmaf(w1, f1.x, acc[2 * j]));
            acc[2 * j + 1] = fmaf(w0, f0.y, fmaf(w1, f1.y, acc[2 * j + 1]));
        }
    }
    if (e < end) {
        const int s0 = g_ssrc[e];
        const float a0 = g_as1[s0 * H1 + h];
        const uint4 v0 = xb[(size_t)s0 * 32 + vidx];
        const float w0 = __expf(lrelu(a0 + ad));
        wsum += w0;
        const __nv_bfloat162* p0 = (const __nv_bfloat162*)&v0;
#pragma unroll
        for (int j = 0; j < 4; j++) {
            float2 f0 = __bfloat1622float2(p0[j]);
            acc[2 * j]     = fmaf(w0, f0.x, acc[2 * j]);
            acc[2 * j + 1] = fmaf(w0, f0.y, acc[2 * j + 1]);
        }
    }
    const float inv = 1.0f / wsum;
    const int c0 = h * C1 + q * 8;
    __nv_bfloat162 ob[4];
#pragma unroll
    for (int j = 0; j < 4; j++) {
        float ox = elu(acc[2 * j] * inv + b1[c0 + 2 * j]);
        float oy = elu(acc[2 * j + 1] * inv + b1[c0 + 2 * j + 1]);
        ob[j] = __floats2bfloat162_rn(ox, oy);
    }
    ((uint4*)g_h1b)[(size_t)n * 32 + vidx] = *(uint4*)ob;
}

// ---------------- GEMM2 HMMA: 128x16x256, fused attention epilogue --------------
#define G2_ST   264
#define G2_ASZ  (128 * G2_ST * 2)
#define G2_BSZ  (16 * G2_ST * 2)
#define G2_SMEM (G2_ASZ + G2_BSZ)
__global__ void __launch_bounds__(256, 2) k_gemm2(const float* __restrict__ W2,
                                                  const float* __restrict__ att_src2,
                                                  const float* __restrict__ att_dst2) {
    extern __shared__ char smem[];
    char* sA = smem;
    char* sB = smem + G2_ASZ;
    const int tid = threadIdx.x;
    const int wid = tid >> 5;
    const int lane = tid & 31;
    const int bm = blockIdx.x * 128;
    const int g = lane >> 2;
    const int t2 = (lane & 3) * 2;

    // zero B smem (incl padding rows 10..15)
    for (int i = tid; i < G2_BSZ / 4; i += 256) ((uint32_t*)sB)[i] = 0;
    // load A (h1b rows, bf16)
#pragma unroll
    for (int i = 0; i < 16; i++) {
        int idx = tid + i * 256;          // 4096 uint4
        int row = idx >> 5;
        int c16 = idx & 31;
        int grow = bm + row;
        uint4 v = make_uint4(0, 0, 0, 0);
        if (grow < NN) v = *(const uint4*)(g_h1b + (size_t)grow * HC + c16 * 8);
        *(uint4*)(sA + row * (G2_ST * 2) + c16 * 16) = v;
    }
    __syncthreads();
    // load B = W2^T zero-padded: sB[n][k] = W2[k][n]
    for (int idx = tid; idx < HC * CO; idx += 256) {
        int k = idx / CO;
        int n = idx % CO;
        ((__nv_bfloat16*)sB)[n * G2_ST + k] = __float2bfloat16(W2[idx]);
    }
    __syncthreads();

    float a0c[4] = {0.f, 0.f, 0.f, 0.f};   // cols 0..7
    float a1c[4] = {0.f, 0.f, 0.f, 0.f};   // cols 8..15
#pragma unroll
    for (int kk = 0; kk < 16; kk++) {
        const int k0 = kk * 16;
        const int rb = wid * 16;
        uint32_t afr[4];
        afr[0] = *(const uint32_t*)(sA + (rb + g) * (G2_ST * 2) + (k0 + t2) * 2);
        afr[1] = *(const uint32_t*)(sA + (rb + g + 8) * (G2_ST * 2) + (k0 + t2) * 2);
        afr[2] = *(const uint32_t*)(sA + (rb + g) * (G2_ST * 2) + (k0 + 8 + t2) * 2);
        afr[3] = *(const uint32_t*)(sA + (rb + g + 8) * (G2_ST * 2) + (k0 + 8 + t2) * 2);
        uint32_t b0[2], b1[2];
        b0[0] = *(const uint32_t*)(sB + g * (G2_ST * 2) + (k0 + t2) * 2);
        b0[1] = *(const uint32_t*)(sB + g * (G2_ST * 2) + (k0 + 8 + t2) * 2);
        b1[0] = *(const uint32_t*)(sB + (8 + g) * (G2_ST * 2) + (k0 + t2) * 2);
        b1[1] = *(const uint32_t*)(sB + (8 + g) * (G2_ST * 2) + (k0 + 8 + t2) * 2);
        mma16816(a0c, afr, b0);
        mma16816(a1c, afr, b1);
    }

    // epilogue
    const int r0 = bm + wid * 16 + g;
    const int r1 = r0 + 8;
    if (r0 < NN) {
        *(float2*)(g_xh2 + (size_t)r0 * 16 + t2) = make_float2(a0c[0], a0c[1]);
        *(float2*)(g_xh2 + (size_t)r0 * 16 + 8 + t2) = make_float2(a1c[0], a1c[1]);
    }
    if (r1 < NN) {
        *(float2*)(g_xh2 + (size_t)r1 * 16 + t2) = make_float2(a0c[2], a0c[3]);
        *(float2*)(g_xh2 + (size_t)r1 * 16 + 8 + t2) = make_float2(a1c[2], a1c[3]);
    }
    float s0x = att_src2[t2], s0y = att_src2[t2 + 1];
    float d0x = att_dst2[t2], d0y = att_dst2[t2 + 1];
    float s1x = 0.f, s1y = 0.f, d1x = 0.f, d1y = 0.f;
    if (t2 == 0) { s1x = att_src2[8]; s1y = att_src2[9]; d1x = att_dst2[8]; d1y = att_dst2[9]; }
    float ps0 = a0c[0] * s0x + a0c[1] * s0y + a1c[0] * s1x + a1c[1] * s1y;
    float pd0 = a0c[0] * d0x + a0c[1] * d0y + a1c[0] * d1x + a1c[1] * d1y;
    float ps1 = a0c[2] * s0x + a0c[3] * s0y + a1c[2] * s1x + a1c[3] * s1y;
    float pd1 = a0c[2] * d0x + a0c[3] * d0y + a1c[2] * d1x + a1c[3] * d1y;
    ps0 += __shfl_xor_sync(0xffffffffu, ps0, 1);
    pd0 += __shfl_xor_sync(0xffffffffu, pd0, 1);
    ps1 += __shfl_xor_sync(0xffffffffu, ps1, 1);
    pd1 += __shfl_xor_sync(0xffffffffu, pd1, 1);
    ps0 += __shfl_xor_sync(0xffffffffu, ps0, 2);
    pd0 += __shfl_xor_sync(0xffffffffu, pd0, 2);
    ps1 += __shfl_xor_sync(0xffffffffu, ps1, 2);
    pd1 += __shfl_xor_sync(0xffffffffu, pd1, 2);
    if ((lane & 3) == 0) {
        if (r0 < NN) { g_as2[r0] = ps0; g_ad2[r0] = pd0; }
        if (r1 < NN) { g_as2[r1] = ps1; g_ad2[r1] = pd1; }
    }
}

// ---------------- layer-2 aggregation: warp/node, even-odd halves ---------------
__global__ void k_agg2(const int* __restrict__ batch, const float* __restrict__ b2) {
    int warp = threadIdx.x >> 5;
    int lane = threadIdx.x & 31;
    int n = blockIdx.x * 8 + warp;
    if (n >= NN) return;
    const int half = lane >> 4;
    const int i = lane & 15;
    const float ad = g_ad2[n];
    float wsum = 0.f, acc = 0.f;
    if (half == 0) {
        float w = __expf(lrelu(g_as2[n] + ad));
        wsum = w;
        acc = w * g_xh2[(size_t)n * 16 + i];
    }
    const int beg = g_off[n], end = g_off[n + 1];
    for (int e = beg + half; e < end; e += 2) {
        const int s = g_ssrc[e];
        const float we = __expf(lrelu(g_as2[s] + ad));
        wsum += we;
        acc = fmaf(we, g_xh2[(size_t)s * 16 + i], acc);
    }
    wsum += __shfl_xor_sync(0xffffffffu, wsum, 16);
    acc += __shfl_xor_sync(0xffffffffu, acc, 16);
    if (half == 0 && i < CO) {
        float out = elu(acc / wsum + b2[i]);
        atomicAdd(&g_sums[batch[n] * CO + i], out);
    }
    if (lane == 0) atomicAdd(&g_cnt[batch[n]], 1.0f);
}

// ---------------- mean + log_softmax ----------------------------------------------
__global__ void k_final(float* __restrict__ out) {
    int g = threadIdx.x;
    if (g >= NG) return;
    float inv = 1.0f / fmaxf(g_cnt[g], 1.0f);
    float v[CO];
    float mx = -1e30f;
#pragma unroll
    for (int c = 0; c < CO; c++) {
        v[c] = g_sums[g * CO + c] * inv;
        mx = fmaxf(mx, v[c]);
    }
    float s = 0.f;
#pragma unroll
    for (int c = 0; c < CO; c++) s += __expf(v[c] - mx);
    float lse = logf(s) + mx;
#pragma unroll
    for (int c = 0; c < CO; c++) out[g * CO + c] = v[c] - lse;
}

// ---------------- launcher ----------------------------------------------------------
extern "C" void kernel_launch(void* const* d_in, const int* in_sizes, int n_in,
                              void* d_out, int out_size) {
    const float* x        = (const float*)d_in[0];
    const int*   ei       = (const int*)d_in[1];
    const int*   batch    = (const int*)d_in[2];
    const float* W1       = (const float*)d_in[3];
    const float* att_src1 = (const float*)d_in[4];
    const float* att_dst1 = (const float*)d_in[5];
    const float* b1       = (const float*)d_in[6];
    const float* W2       = (const float*)d_in[7];
    const float* att_src2 = (const float*)d_in[8];
    const float* att_dst2 = (const float*)d_in[9];
    const float* b2       = (const float*)d_in[10];
    float* out = (float*)d_out;
    const int E = in_sizes[1] / 2;

    cudaFuncSetAttribute(k_gemm1, cudaFuncAttributeMaxDynamicSharedMemorySize, G1_SMEM);
    cudaFuncSetAttribute(k_gemm2, cudaFuncAttributeMaxDynamicSharedMemorySize, G2_SMEM);

    k_zero<<<(NN + 255) / 256, 256>>>();
    k_hist<<<(E + 255) / 256, 256>>>(ei, E);
    k_cvt_w<<<dim3(FIN / 32, HC / 32), dim3(32, 32)>>>(W1);
    k_gemm1<<<(NN + 63) / 64, 256, G1_SMEM>>>(x, att_src1, att_dst1);  // profiled slot
    k_scan1<<<NBLK, 256>>>();
    k_scan2<<<1, 256>>>();
    k_scan3<<<NBLK, 256>>>();
    k_scatter<<<(E + 255) / 256, 256>>>(ei, E);
    k_agg1<<<(NN + 7) / 8, 256>>>(b1);
    k_gemm2<<<(NN + 127) / 128, 256, G2_SMEM>>>(W2, att_src2, att_dst2);
    k_agg2<<<(NN + 7) / 8, 256>>>(batch, b2);
    k_final<<<1, NG>>>(out);
}

// round 7
// speedup vs baseline: 3.4329x; 1.0154x over previous
#include <cuda_runtime.h>
#include <cuda_bf16.h>
#include <cstdint>

#define NN   50000
#define EE   800000
#define FIN  128
#define H1   8
#define C1   32
#define HC   256
#define CO   10
#define NG   128
#define NEG_SLOPE 0.2f
#define NBLK 196          // ceil(NN/256)

// ---------------- scratch ----------------------------------------------------
__device__ __nv_bfloat16  g_xhb[(size_t)NN * HC];
__device__ __nv_bfloat16  g_h1b[(size_t)NN * HC];
__device__ __nv_bfloat16  g_w1b[(size_t)HC * FIN];
__device__ float g_as1[NN * H1];
__device__ float g_ad1[NN * H1];
__device__ int   g_deg[NN];
__device__ int   g_off[NN + 1];
__device__ int   g_cur[NN];
__device__ int   g_part[NBLK];
__device__ int   g_ssrc[EE];
__device__ float g_xh2[(size_t)NN * 16];
__device__ float g_as2[NN];
__device__ float g_ad2[NN];
__device__ float g_sums[NG * CO];
__device__ float g_cnt[NG];

__device__ __forceinline__ float lrelu(float x) {
    return fmaxf(x, 0.0f) + NEG_SLOPE * fminf(x, 0.0f);
}
__device__ __forceinline__ float elu(float x) {
    return x > 0.0f ? x : (__expf(x) - 1.0f);
}
__device__ __forceinline__ void mma16816(float* d, const uint32_t* a, const uint32_t* b) {
    asm volatile(
        "mma.sync.aligned.m16n8k16.row.col.f32.bf16.bf16.f32 "
        "{%0,%1,%2,%3}, {%4,%5,%6,%7}, {%8,%9}, {%0,%1,%2,%3};"
        : "+f"(d[0]), "+f"(d[1]), "+f"(d[2]), "+f"(d[3])
        : "r"(a[0]), "r"(a[1]), "r"(a[2]), "r"(a[3]), "r"(b[0]), "r"(b[1]));
}
__device__ __forceinline__ void ldsm4(uint32_t& r0, uint32_t& r1, uint32_t& r2,
                                      uint32_t& r3, uint32_t addr) {
    asm volatile("ldmatrix.sync.aligned.m8n8.x4.shared.b16 {%0,%1,%2,%3}, [%4];"
                 : "=r"(r0), "=r"(r1), "=r"(r2), "=r"(r3) : "r"(addr));
}

// ---------------- 0. zero ----------------------------------------------------
__global__ void k_zero() {
    int i = blockIdx.x * blockDim.x + threadIdx.x;
    if (i < NN) g_deg[i] = 0;
    if (i < NG * CO) g_sums[i] = 0.0f;
    if (i < NG) g_cnt[i] = 0.0f;
}

// ---------------- W1 transpose+convert ----------------------------------------
__global__ void k_cvt_w(const float* __restrict__ W1) {
    __shared__ float s[32][33];
    int k0 = blockIdx.x * 32;
    int n0 = blockIdx.y * 32;
    int tx = threadIdx.x, ty = threadIdx.y;
    s[ty][tx] = W1[(size_t)(k0 + ty) * HC + n0 + tx];
    __syncthreads();
    g_w1b[(size_t)(n0 + ty) * FIN + k0 + tx] = __float2bfloat16(s[tx][ty]);
}

// ---------------- GEMM1 HMMA + ldmatrix: CTA tile 64x256, K=128 ----------------
#define G1_ST   136
#define G1_ST2  (G1_ST * 2)
#define G1_ASZ  (64 * G1_ST2)
#define G1_SMEM (G1_ASZ + 256 * G1_ST2)
__global__ void __launch_bounds__(256, 2) k_gemm1(const float* __restrict__ x,
                                                  const float* __restrict__ att_src,
                                                  const float* __restrict__ att_dst) {
    extern __shared__ char smem[];
    char* sA = smem;
    char* sB = smem + G1_ASZ;
    const int tid = threadIdx.x;
    const int wid = tid >> 5;
    const int lane = tid & 31;
    const int bm = blockIdx.x * 64;
    const int mw = wid >> 2;
    const int nw = wid & 3;
    const int g = lane >> 2;
    const int t2 = (lane & 3) * 2;

#pragma unroll
    for (int i = 0; i < 8; i++) {
        int idx = tid + i * 256;
        int row = idx >> 5;
        int c4 = idx & 31;
        float4 v = make_float4(0.f, 0.f, 0.f, 0.f);
        int grow = bm + row;
        if (grow < NN) v = *(const float4*)(x + (size_t)grow * FIN + c4 * 4);
        __nv_bfloat162 b0 = __floats2bfloat162_rn(v.x, v.y);
        __nv_bfloat162 b1 = __floats2bfloat162_rn(v.z, v.w);
        uint2 p = make_uint2(*(uint32_t*)&b0, *(uint32_t*)&b1);
        *(uint2*)(sA + row * G1_ST2 + c4 * 8) = p;
    }
#pragma unroll
    for (int i = 0; i < 16; i++) {
        int idx = tid + i * 256;
        int row = idx >> 4;
        int c16 = idx & 15;
        uint4 v = *(const uint4*)(g_w1b + (size_t)row * FIN + c16 * 8);
        *(uint4*)(sB + row * G1_ST2 + c16 * 16) = v;
    }
    __syncthreads();

    // ldmatrix base addresses
    const uint32_t sAu = (uint32_t)__cvta_generic_to_shared(sA);
    const uint32_t sBu = (uint32_t)__cvta_generic_to_shared(sB);
    const int l15 = lane & 15;
    const int kgA = ((lane >> 4) & 1) * 16;            // k-offset bytes (8 elems)
    uint32_t aAddr[2];
#pragma unroll
    for (int mt = 0; mt < 2; mt++)
        aAddr[mt] = sAu + (mw * 32 + mt * 16 + l15) * G1_ST2 + kgA;
    const int rB = (lane & 7) + ((lane >> 4) & 1) * 8;
    const int kgB = ((lane >> 3) & 1) * 16;
    uint32_t bAddr[4];
#pragma unroll
    for (int jp = 0; jp < 4; jp++)
        bAddr[jp] = sBu + (nw * 64 + jp * 16 + rB) * G1_ST2 + kgB;

    float acc[2][8][4];
#pragma unroll
    for (int mt = 0; mt < 2; mt++)
#pragma unroll
        for (int j = 0; j < 8; j++)
#pragma unroll
            for (int q = 0; q < 4; q++) acc[mt][j][q] = 0.f;

#pragma unroll
    for (int kk = 0; kk < 8; kk++) {
        const uint32_t ko = kk * 32;
        uint32_t afr[2][4];
#pragma unroll
        for (int mt = 0; mt < 2; mt++)
            ldsm4(afr[mt][0], afr[mt][1], afr[mt][2], afr[mt][3], aAddr[mt] + ko);
        uint32_t bfr[8][2];
#pragma unroll
        for (int jp = 0; jp < 4; jp++)
            ldsm4(bfr[2 * jp][0], bfr[2 * jp][1], bfr[2 * jp + 1][0], bfr[2 * jp + 1][1],
                  bAddr[jp] + ko);
#pragma unroll
        for (int mt = 0; mt < 2; mt++)
#pragma unroll
            for (int j = 0; j < 8; j++) mma16816(acc[mt][j], afr[mt], bfr[j]);
    }

#pragma unroll
    for (int mt = 0; mt < 2; mt++) {
        const int r0 = bm + mw * 32 + mt * 16 + g;
        const int r1 = r0 + 8;
#pragma unroll
        for (int j = 0; j < 8; j++) {
            const int c = nw * 64 + j * 8 + t2;
            __nv_bfloat162 v0 = __floats2bfloat162_rn(acc[mt][j][0], acc[mt][j][1]);
            __nv_bfloat162 v1 = __floats2bfloat162_rn(acc[mt][j][2], acc[mt][j][3]);
            if (r0 < NN) *(uint32_t*)(g_xhb + (size_t)r0 * HC + c) = *(uint32_t*)&v0;
            if (r1 < NN) *(uint32_t*)(g_xhb + (size_t)r1 * HC + c) = *(uint32_t*)&v1;
        }
#pragma unroll
        for (int hh = 0; hh < 2; hh++) {
            float ps0 = 0.f, pd0 = 0.f, ps1 = 0.f, pd1 = 0.f;
#pragma unroll
            for (int jj = 0; jj < 4; jj++) {
                const int j = hh * 4 + jj;
                const int c = nw * 64 + j * 8 + t2;
                float2 s2 = *(const float2*)(att_src + c);
                float2 d2 = *(const float2*)(att_dst + c);
                ps0 = fmaf(acc[mt][j][0], s2.x, fmaf(acc[mt][j][1], s2.y, ps0));
                pd0 = fmaf(acc[mt][j][0], d2.x, fmaf(acc[mt][j][1], d2.y, pd0));
                ps1 = fmaf(acc[mt][j][2], s2.x, fmaf(acc[mt][j][3], s2.y, ps1));
                pd1 = fmaf(acc[mt][j][2], d2.x, fmaf(acc[mt][j][3], d2.y, pd1));
            }
            ps0 += __shfl_xor_sync(0xffffffffu, ps0, 1);
            pd0 += __shfl_xor_sync(0xffffffffu, pd0, 1);
            ps1 += __shfl_xor_sync(0xffffffffu, ps1, 1);
            pd1 += __shfl_xor_sync(0xffffffffu, pd1, 1);
            ps0 += __shfl_xor_sync(0xffffffffu, ps0, 2);
            pd0 += __shfl_xor_sync(0xffffffffu, pd0, 2);
            ps1 += __shfl_xor_sync(0xffffffffu, ps1, 2);
            pd1 += __shfl_xor_sync(0xffffffffu, pd1, 2);
            const int h = nw * 2 + hh;
            if ((lane & 3) == 0) {
                if (r0 < NN) { g_as1[r0 * H1 + h] = ps0; g_ad1[r0 * H1 + h] = pd0; }
                if (r1 < NN) { g_as1[r1 * H1 + h] = ps1; g_ad1[r1 * H1 + h] = pd1; }
            }
        }
    }
}

// ---------------- CSR build ----------------------------------------------------
__global__ void k_hist(const int* __restrict__ ei, int E) {
    int e = blockIdx.x * blockDim.x + threadIdx.x;
    if (e < E) atomicAdd(&g_deg[ei[E + e]], 1);
}
__global__ void k_scan1() {
    __shared__ int s[256];
    int i = blockIdx.x * 256 + threadIdx.x;
    int v = (i < NN) ? g_deg[i] : 0;
    s[threadIdx.x] = v;
    __syncthreads();
    for (int o = 128; o; o >>= 1) {
        if (threadIdx.x < o) s[threadIdx.x] += s[threadIdx.x + o];
        __syncthreads();
    }
    if (threadIdx.x == 0) g_part[blockIdx.x] = s[0];
}
__global__ void k_scan2() {
    __shared__ int s[256];
    int t = threadIdx.x;
    int v = (t < NBLK) ? g_part[t] : 0;
    s[t] = v;
    __syncthreads();
    for (int o = 1; o < 256; o <<= 1) {
        int u = (t >= o) ? s[t - o] : 0;
        __syncthreads();
        s[t] += u;
        __syncthreads();
    }
    if (t < NBLK) g_part[t] = s[t] - v;
}
__global__ void k_scan3() {
    __shared__ int s[256];
    int t = threadIdx.x;
    int i = blockIdx.x * 256 + t;
    int v = (i < NN) ? g_deg[i] : 0;
    s[t] = v;
    __syncthreads();
    for (int o = 1; o < 256; o <<= 1) {
        int u = (t >= o) ? s[t - o] : 0;
        __syncthreads();
        s[t] += u;
        __syncthreads();
    }
    int base = g_part[blockIdx.x];
    if (i < NN) {
        int off = base + s[t] - v;
        g_off[i] = off;
        g_cur[i] = off;
        if (i == NN - 1) g_off[NN] = base + s[t];
    }
}
__global__ void k_scatter(const int* __restrict__ ei, int E) {
    int e = blockIdx.x * blockDim.x + threadIdx.x;
    if (e < E) {
        int d = ei[E + e];
        int p = atomicAdd(&g_cur[d], 1);
        g_ssrc[p] = ei[e];
    }
}

// ---------------- layer-1 aggregation: warp per node ----------------------------
__global__ void k_agg1(const float* __restrict__ b1) {
    const int warp = threadIdx.x >> 5;
    const int lane = threadIdx.x & 31;
    const int n = blockIdx.x * 8 + warp;
    if (n >= NN) return;
    const int h = lane >> 2;
    const int q = lane & 3;
    const int vidx = h * 4 + q;
    const uint4* xb = (const uint4*)g_xhb;

    const float ad = g_ad1[n * H1 + h];
    float w = __expf(lrelu(g_as1[n * H1 + h] + ad));
    float wsum = w;
    float acc[8];
    {
        uint4 sv = xb[(size_t)n * 32 + vidx];
        const __nv_bfloat162* bp = (const __nv_bfloat162*)&sv;
#pragma unroll
        for (int j = 0; j < 4; j++) {
            float2 f = __bfloat1622float2(bp[j]);
            acc[2 * j] = w * f.x;
            acc[2 * j + 1] = w * f.y;
        }
    }
    int e = g_off[n];
    const int end = g_off[n + 1];
    for (; e + 2 <= end; e += 2) {
        const int s0 = g_ssrc[e];
        const int s1 = g_ssrc[e + 1];
        const float a0 = g_as1[s0 * H1 + h];
        const float a1 = g_as1[s1 * H1 + h];
        const uint4 v0 = xb[(size_t)s0 * 32 + vidx];
        const uint4 v1 = xb[(size_t)s1 * 32 + vidx];
        const float w0 = __expf(lrelu(a0 + ad));
        const float w1 = __expf(lrelu(a1 + ad));
        wsum += w0 + w1;
        const __nv_bfloat162* p0 = (const __nv_bfloat162*)&v0;
        const __nv_bfloat162* p1 = (const __nv_bfloat162*)&v1;
#pragma unroll
        for (int j = 0; j < 4; j++) {
            float2 f0 = __bfloat1622float2(p0[j]);
            float2 f1 = __bfloat1622float2(p1[j]);
            acc[2 * j]     = fmaf(w0, f0.x, fmaf(w1, f1.x, acc[2 * j]));
            acc[2 * j + 1] = fmaf(w0, f0.y, fmaf(w1, f1.y, acc[2 * j + 1]));
        }
    }
    if (e < end) {
        const int s0 = g_ssrc[e];
        const float a0 = g_as1[s0 * H1 + h];
        const uint4 v0 = xb[(size_t)s0 * 32 + vidx];
        const float w0 = __expf(lrelu(a0 + ad));
        wsum += w0;
        const __nv_bfloat162* p0 = (const __nv_bfloat162*)&v0;
#pragma unroll
        for (int j = 0; j < 4; j++) {
            float2 f0 = __bfloat1622float2(p0[j]);
            acc[2 * j]     = fmaf(w0, f0.x, acc[2 * j]);
            acc[2 * j + 1] = fmaf(w0, f0.y, acc[2 * j + 1]);
        }
    }
    const float inv = 1.0f / wsum;
    const int c0 = h * C1 + q * 8;
    __nv_bfloat162 ob[4];
#pragma unroll
    for (int j = 0; j < 4; j++) {
        float ox = elu(acc[2 * j] * inv + b1[c0 + 2 * j]);
        float oy = elu(acc[2 * j + 1] * inv + b1[c0 + 2 * j + 1]);
        ob[j] = __floats2bfloat162_rn(ox, oy);
    }
    ((uint4*)g_h1b)[(size_t)n * 32 + vidx] = *(uint4*)ob;
}

// ---------------- GEMM2 HMMA: 128x16x256, fused attention epilogue --------------
#define G2_ST   264
#define G2_ASZ  (128 * G2_ST * 2)
#define G2_BSZ  (16 * G2_ST * 2)
#define G2_SMEM (G2_ASZ + G2_BSZ)
__global__ void __launch_bounds__(256, 2) k_gemm2(const float* __restrict__ W2,
                                                  const float* __restrict__ att_src2,
                                                  const float* __restrict__ att_dst2) {
    extern __shared__ char smem[];
    char* sA = smem;
    char* sB = smem + G2_ASZ;
    const int tid = threadIdx.x;
    const int wid = tid >> 5;
    const int lane = tid & 31;
    const int bm = blockIdx.x * 128;
    const int g = lane >> 2;
    const int t2 = (lane & 3) * 2;

    for (int i = tid; i < G2_BSZ / 4; i += 256) ((uint32_t*)sB)[i] = 0;
#pragma unroll
    for (int i = 0; i < 16; i++) {
        int idx = tid + i * 256;
        int row = idx >> 5;
        int c16 = idx & 31;
        int grow = bm + row;
        uint4 v = make_uint4(0, 0, 0, 0);
        if (grow < NN) v = *(const uint4*)(g_h1b + (size_t)grow * HC + c16 * 8);
        *(uint4*)(sA + row * (G2_ST * 2) + c16 * 16) = v;
    }
    __syncthreads();
    for (int idx = tid; idx < HC * CO; idx += 256) {
        int k = idx / CO;
        int n = idx % CO;
        ((__nv_bfloat16*)sB)[n * G2_ST + k] = __float2bfloat16(W2[idx]);
    }
    __syncthreads();

    float a0c[4] = {0.f, 0.f, 0.f, 0.f};
    float a1c[4] = {0.f, 0.f, 0.f, 0.f};
#pragma unroll
    for (int kk = 0; kk < 16; kk++) {
        const int k0 = kk * 16;
        const int rb = wid * 16;
        uint32_t afr[4];
        afr[0] = *(const uint32_t*)(sA + (rb + g) * (G2_ST * 2) + (k0 + t2) * 2);
        afr[1] = *(const uint32_t*)(sA + (rb + g + 8) * (G2_ST * 2) + (k0 + t2) * 2);
        afr[2] = *(const uint32_t*)(sA + (rb + g) * (G2_ST * 2) + (k0 + 8 + t2) * 2);
        afr[3] = *(const uint32_t*)(sA + (rb + g + 8) * (G2_ST * 2) + (k0 + 8 + t2) * 2);
        uint32_t b0[2], b1[2];
        b0[0] = *(const uint32_t*)(sB + g * (G2_ST * 2) + (k0 + t2) * 2);
        b0[1] = *(const uint32_t*)(sB + g * (G2_ST * 2) + (k0 + 8 + t2) * 2);
        b1[0] = *(const uint32_t*)(sB + (8 + g) * (G2_ST * 2) + (k0 + t2) * 2);
        b1[1] = *(const uint32_t*)(sB + (8 + g) * (G2_ST * 2) + (k0 + 8 + t2) * 2);
        mma16816(a0c, afr, b0);
        mma16816(a1c, afr, b1);
    }

    const int r0 = bm + wid * 16 + g;
    const int r1 = r0 + 8;
    if (r0 < NN) {
        *(float2*)(g_xh2 + (size_t)r0 * 16 + t2) = make_float2(a0c[0], a0c[1]);
        *(float2*)(g_xh2 + (size_t)r0 * 16 + 8 + t2) = make_float2(a1c[0], a1c[1]);
    }
    if (r1 < NN) {
        *(float2*)(g_xh2 + (size_t)r1 * 16 + t2) = make_float2(a0c[2], a0c[3]);
        *(float2*)(g_xh2 + (size_t)r1 * 16 + 8 + t2) = make_float2(a1c[2], a1c[3]);
    }
    float s0x = att_src2[t2], s0y = att_src2[t2 + 1];
    float d0x = att_dst2[t2], d0y = att_dst2[t2 + 1];
    float s1x = 0.f, s1y = 0.f, d1x = 0.f, d1y = 0.f;
    if (t2 == 0) { s1x = att_src2[8]; s1y = att_src2[9]; d1x = att_dst2[8]; d1y = att_dst2[9]; }
    float ps0 = a0c[0] * s0x + a0c[1] * s0y + a1c[0] * s1x + a1c[1] * s1y;
    float pd0 = a0c[0] * d0x + a0c[1] * d0y + a1c[0] * d1x + a1c[1] * d1y;
    float ps1 = a0c[2] * s0x + a0c[3] * s0y + a1c[2] * s1x + a1c[3] * s1y;
    float pd1 = a0c[2] * d0x + a0c[3] * d0y + a1c[2] * d1x + a1c[3] * d1y;
    ps0 += __shfl_xor_sync(0xffffffffu, ps0, 1);
    pd0 += __shfl_xor_sync(0xffffffffu, pd0, 1);
    ps1 += __shfl_xor_sync(0xffffffffu, ps1, 1);
    pd1 += __shfl_xor_sync(0xffffffffu, pd1, 1);
    ps0 += __shfl_xor_sync(0xffffffffu, ps0, 2);
    pd0 += __shfl_xor_sync(0xffffffffu, pd0, 2);
    ps1 += __shfl_xor_sync(0xffffffffu, ps1, 2);
    pd1 += __shfl_xor_sync(0xffffffffu, pd1, 2);
    if ((lane & 3) == 0) {
        if (r0 < NN) { g_as2[r0] = ps0; g_ad2[r0] = pd0; }
        if (r1 < NN) { g_as2[r1] = ps1; g_ad2[r1] = pd1; }
    }
}

// ---------------- layer-2 aggregation ---------------------------------------------
__global__ void k_agg2(const int* __restrict__ batch, const float* __restrict__ b2) {
    int warp = threadIdx.x >> 5;
    int lane = threadIdx.x & 31;
    int n = blockIdx.x * 8 + warp;
    if (n >= NN) return;
    const int half = lane >> 4;
    const int i = lane & 15;
    const float ad = g_ad2[n];
    float wsum = 0.f, acc = 0.f;
    if (half == 0) {
        float w = __expf(lrelu(g_as2[n] + ad));
        wsum = w;
        acc = w * g_xh2[(size_t)n * 16 + i];
    }
    const int beg = g_off[n], end = g_off[n + 1];
    for (int e = beg + half; e < end; e += 2) {
        const int s = g_ssrc[e];
        const float we = __expf(lrelu(g_as2[s] + ad));
        wsum += we;
        acc = fmaf(we, g_xh2[(size_t)s * 16 + i], acc);
    }
    wsum += __shfl_xor_sync(0xffffffffu, wsum, 16);
    acc += __shfl_xor_sync(0xffffffffu, acc, 16);
    if (half == 0 && i < CO) {
        float out = elu(acc / wsum + b2[i]);
        atomicAdd(&g_sums[batch[n] * CO + i], out);
    }
    if (lane == 0) atomicAdd(&g_cnt[batch[n]], 1.0f);
}

// ---------------- mean + log_softmax ----------------------------------------------
__global__ void k_final(float* __restrict__ out) {
    int g = threadIdx.x;
    if (g >= NG) return;
    float inv = 1.0f / fmaxf(g_cnt[g], 1.0f);
    float v[CO];
    float mx = -1e30f;
#pragma unroll
    for (int c = 0; c < CO; c++) {
        v[c] = g_sums[g * CO + c] * inv;
        mx = fmaxf(mx, v[c]);
    }
    float s = 0.f;
#pragma unroll
    for (int c = 0; c < CO; c++) s += __expf(v[c] - mx);
    float lse = logf(s) + mx;
#pragma unroll
    for (int c = 0; c < CO; c++) out[g * CO + c] = v[c] - lse;
}

// ---------------- launcher ----------------------------------------------------------
extern "C" void kernel_launch(void* const* d_in, const int* in_sizes, int n_in,
                              void* d_out, int out_size) {
    const float* x        = (const float*)d_in[0];
    const int*   ei       = (const int*)d_in[1];
    const int*   batch    = (const int*)d_in[2];
    const float* W1       = (const float*)d_in[3];
    const float* att_src1 = (const float*)d_in[4];
    const float* att_dst1 = (const float*)d_in[5];
    const float* b1       = (const float*)d_in[6];
    const float* W2       = (const float*)d_in[7];
    const float* att_src2 = (const float*)d_in[8];
    const float* att_dst2 = (const float*)d_in[9];
    const float* b2       = (const float*)d_in[10];
    float* out = (float*)d_out;
    const int E = in_sizes[1] / 2;

    static cudaStream_t s1 = nullptr;
    static cudaEvent_t e0 = nullptr, e1 = nullptr;
    if (!s1) {
        cudaStreamCreateWithFlags(&s1, cudaStreamNonBlocking);
        cudaEventCreateWithFlags(&e0, cudaEventDisableTiming);
        cudaEventCreateWithFlags(&e1, cudaEventDisableTiming);
        cudaFuncSetAttribute(k_gemm1, cudaFuncAttributeMaxDynamicSharedMemorySize, G1_SMEM);
        cudaFuncSetAttribute(k_gemm2, cudaFuncAttributeMaxDynamicSharedMemorySize, G2_SMEM);
    }

    // main chain: zero -> hist -> scans -> scatter (CSR build)
    cudaEventRecord(e0, 0);
    k_zero<<<(NN + 255) / 256, 256>>>();
    k_hist<<<(E + 255) / 256, 256>>>(ei, E);
    // side chain (overlaps with CSR build): W1 convert -> GEMM1
    cudaStreamWaitEvent(s1, e0, 0);
    k_cvt_w<<<dim3(FIN / 32, HC / 32), dim3(32, 32), 0, s1>>>(W1);
    k_gemm1<<<(NN + 63) / 64, 256, G1_SMEM, s1>>>(x, att_src1, att_dst1);  // 4th launch (profiled)
    cudaEventRecord(e1, s1);
    // continue CSR build on main
    k_scan1<<<NBLK, 256>>>();
    k_scan2<<<1, 256>>>();
    k_scan3<<<NBLK, 256>>>();
    k_scatter<<<(E + 255) / 256, 256>>>(ei, E);
    // join: agg1 needs GEMM1 outputs + CSR
    cudaStreamWaitEvent(0, e1, 0);
    k_agg1<<<(NN + 7) / 8, 256>>>(b1);
    k_gemm2<<<(NN + 127) / 128, 256, G2_SMEM>>>(W2, att_src2, att_dst2);
    k_agg2<<<(NN + 7) / 8, 256>>>(batch, b2);
    k_final<<<1, NG>>>(out);
}